// round 1
// baseline (speedup 1.0000x reference)
#include <cuda_runtime.h>
#include <math.h>

#define NB 32
#define NS 1024
#define NH 1024
#define ND 128

// scratch for q,k,v (48MB total) — __device__ globals per allocation rules
__device__ float g_q[NB * NS * ND];
__device__ float g_k[NB * NS * ND];
__device__ float g_v[NB * NS * ND];

// ---------------------------------------------------------------------------
// QKV projection: out[b,s,:] = X[b,s,:] @ W + bias   (M=32768, N=128, K=1024)
// BM=64, BN=128, BK=16, 256 threads, 4x8 thread tile
// ---------------------------------------------------------------------------
__global__ __launch_bounds__(256) void qkv_kernel(
    const float* __restrict__ X,
    const float* __restrict__ Wq, const float* __restrict__ bq,
    const float* __restrict__ Wk, const float* __restrict__ bk,
    const float* __restrict__ Wv, const float* __restrict__ bv)
{
    __shared__ float As[16][68];    // A tile transposed: As[k][m], pad 4
    __shared__ float Bs[16][128];   // B tile natural:   Bs[k][n]

    const float* W;
    const float* bias;
    float* out;
    if (blockIdx.y == 0)      { W = Wq; bias = bq; out = g_q; }
    else if (blockIdx.y == 1) { W = Wk; bias = bk; out = g_k; }
    else                      { W = Wv; bias = bv; out = g_v; }

    const int t  = threadIdx.x;
    const int m0 = blockIdx.x * 64;

    const int ar  = t >> 2;         // 0..63 : A load row
    const int ak  = (t & 3) * 4;    // 0..12 : A load k-offset
    const int bkk = t >> 4;         // 0..15 : B load k-row
    const int bc  = (t & 15) * 8;   // 0..120: B load col

    const int r = (t >> 4) * 4;     // compute rows r..r+3
    const int c = (t & 15) * 8;     // compute cols c..c+7

    float acc[4][8];
    #pragma unroll
    for (int i = 0; i < 4; i++)
        #pragma unroll
        for (int j = 0; j < 8; j++) acc[i][j] = 0.f;

    for (int k0 = 0; k0 < NH; k0 += 16) {
        float4 av = *(const float4*)&X[(size_t)(m0 + ar) * NH + k0 + ak];
        As[ak + 0][ar] = av.x;
        As[ak + 1][ar] = av.y;
        As[ak + 2][ar] = av.z;
        As[ak + 3][ar] = av.w;
        float4 b0 = *(const float4*)&W[(size_t)(k0 + bkk) * ND + bc];
        float4 b1 = *(const float4*)&W[(size_t)(k0 + bkk) * ND + bc + 4];
        *(float4*)&Bs[bkk][bc]     = b0;
        *(float4*)&Bs[bkk][bc + 4] = b1;
        __syncthreads();

        #pragma unroll
        for (int kk = 0; kk < 16; kk++) {
            float4 a  = *(const float4*)&As[kk][r];
            float4 u0 = *(const float4*)&Bs[kk][c];
            float4 u1 = *(const float4*)&Bs[kk][c + 4];
            float aa[4] = {a.x, a.y, a.z, a.w};
            float bb[8] = {u0.x, u0.y, u0.z, u0.w, u1.x, u1.y, u1.z, u1.w};
            #pragma unroll
            for (int i = 0; i < 4; i++)
                #pragma unroll
                for (int j = 0; j < 8; j++)
                    acc[i][j] += aa[i] * bb[j];
        }
        __syncthreads();
    }

    #pragma unroll
    for (int i = 0; i < 4; i++) {
        float4 o0, o1;
        o0.x = acc[i][0] + bias[c + 0];
        o0.y = acc[i][1] + bias[c + 1];
        o0.z = acc[i][2] + bias[c + 2];
        o0.w = acc[i][3] + bias[c + 3];
        o1.x = acc[i][4] + bias[c + 4];
        o1.y = acc[i][5] + bias[c + 5];
        o1.z = acc[i][6] + bias[c + 6];
        o1.w = acc[i][7] + bias[c + 7];
        *(float4*)&out[(size_t)(m0 + r + i) * ND + c]     = o0;
        *(float4*)&out[(size_t)(m0 + r + i) * ND + c + 4] = o1;
    }
}

// ---------------------------------------------------------------------------
// Attention: per CTA = (batch b, 32-query tile).
// smem: Qs[32][128] + KV[128][129] + Ss[32][1032] + red[32]  (~215KB)
// ---------------------------------------------------------------------------
#define SS_STRIDE 1032
#define ATTN_SMEM_FLOATS (32 * 128 + 128 * 129 + 32 * SS_STRIDE + 32)
#define ATTN_SMEM_BYTES  (ATTN_SMEM_FLOATS * 4)

__global__ __launch_bounds__(256) void attn_kernel(float* __restrict__ o_out,
                                                   float* __restrict__ o_probs)
{
    extern __shared__ float sm[];
    float* Qs  = sm;                     // 32*128
    float* KV  = Qs + 32 * 128;          // 128*129 (stride 129 for K, 128 for V)
    float* Ss  = KV + 128 * 129;         // 32*1032
    float* red = Ss + 32 * SS_STRIDE;    // 32 (1/rowsum)

    const int t  = threadIdx.x;
    const int b  = blockIdx.y;
    const int q0 = blockIdx.x * 32;
    const float scale = 0.08838834764831845f;  // 1/sqrt(128)

    // ---- load Q tile (pre-scaled) ----
    #pragma unroll
    for (int it = 0; it < 4; it++) {
        int f  = t + it * 256;          // float4 id 0..1023
        int rr = f >> 5;
        int c4 = (f & 31) * 4;
        float4 v = *(const float4*)&g_q[((size_t)(b * NS + q0 + rr)) * ND + c4];
        v.x *= scale; v.y *= scale; v.z *= scale; v.w *= scale;
        *(float4*)&Qs[rr * 128 + c4] = v;
    }

    const int ty = t >> 5;   // 0..7
    const int tx = t & 31;   // 0..31

    // ---- phase 1: scores S = Q @ K^T (pre-scaled) ----
    for (int kc = 0; kc < 8; kc++) {
        #pragma unroll
        for (int it = 0; it < 16; it++) {
            int f   = t + it * 256;     // float4 id 0..4095
            int key = f >> 5;
            int d4  = (f & 31) * 4;
            float4 v = *(const float4*)&g_k[((size_t)(b * NS + kc * 128 + key)) * ND + d4];
            float* dst = &KV[key * 129 + d4];
            dst[0] = v.x; dst[1] = v.y; dst[2] = v.z; dst[3] = v.w;
        }
        __syncthreads();

        float acc[4][4];
        #pragma unroll
        for (int i = 0; i < 4; i++)
            #pragma unroll
            for (int j = 0; j < 4; j++) acc[i][j] = 0.f;

        #pragma unroll 4
        for (int kk = 0; kk < 128; kk++) {
            float qv[4], kv4[4];
            #pragma unroll
            for (int i = 0; i < 4; i++) qv[i] = Qs[(ty * 4 + i) * 128 + kk];
            #pragma unroll
            for (int j = 0; j < 4; j++) kv4[j] = KV[(tx + 32 * j) * 129 + kk];
            #pragma unroll
            for (int i = 0; i < 4; i++)
                #pragma unroll
                for (int j = 0; j < 4; j++)
                    acc[i][j] += qv[i] * kv4[j];
        }
        #pragma unroll
        for (int i = 0; i < 4; i++)
            #pragma unroll
            for (int j = 0; j < 4; j++)
                Ss[(ty * 4 + i) * SS_STRIDE + kc * 128 + tx + 32 * j] = acc[i][j];
        __syncthreads();
    }

    // ---- softmax: exp(s - max) kept unnormalized in Ss, 1/sum in red ----
    {
        int rr = t >> 3;       // row 0..31
        int j  = t & 7;        // 8 threads per row
        float* row = &Ss[rr * SS_STRIDE];
        float mx = -1e30f;
        #pragma unroll 8
        for (int tt = 0; tt < 128; tt++) mx = fmaxf(mx, row[j + 8 * tt]);
        #pragma unroll
        for (int o = 1; o < 8; o <<= 1) mx = fmaxf(mx, __shfl_xor_sync(0xffffffffu, mx, o));
        float sum = 0.f;
        #pragma unroll 8
        for (int tt = 0; tt < 128; tt++) {
            int idx = j + 8 * tt;
            float e = __expf(row[idx] - mx);
            row[idx] = e;
            sum += e;
        }
        #pragma unroll
        for (int o = 1; o < 8; o <<= 1) sum += __shfl_xor_sync(0xffffffffu, sum, o);
        if (j == 0) red[rr] = 1.f / sum;
    }
    __syncthreads();

    // ---- coalesced probs write ----
    #pragma unroll 4
    for (int it = 0; it < 32; it++) {
        int f  = t + it * 256;          // float4 id 0..8191
        int rr = f >> 8;
        int c4 = (f & 255) * 4;
        float ri = red[rr];
        float4 e = *(const float4*)&Ss[rr * SS_STRIDE + c4];
        e.x *= ri; e.y *= ri; e.z *= ri; e.w *= ri;
        *(float4*)&o_probs[((size_t)(b * NS + q0 + rr)) * NS + c4] = e;
    }
    __syncthreads();

    // ---- phase 3: O = (exp-S @ V) * 1/sum ----
    float oacc[4][4];
    #pragma unroll
    for (int i = 0; i < 4; i++)
        #pragma unroll
        for (int j = 0; j < 4; j++) oacc[i][j] = 0.f;

    for (int vc = 0; vc < 8; vc++) {
        #pragma unroll
        for (int it = 0; it < 16; it++) {
            int f  = t + it * 256;
            int kv = f >> 5;
            int d4 = (f & 31) * 4;
            float4 v = *(const float4*)&g_v[((size_t)(b * NS + vc * 128 + kv)) * ND + d4];
            *(float4*)&KV[kv * 128 + d4] = v;   // stride 128 here
        }
        __syncthreads();

        #pragma unroll 4
        for (int kv = 0; kv < 128; kv++) {
            float4 vv = *(const float4*)&KV[kv * 128 + tx * 4];
            #pragma unroll
            for (int i = 0; i < 4; i++) {
                float p = Ss[(ty * 4 + i) * SS_STRIDE + vc * 128 + kv];
                oacc[i][0] += p * vv.x;
                oacc[i][1] += p * vv.y;
                oacc[i][2] += p * vv.z;
                oacc[i][3] += p * vv.w;
            }
        }
        __syncthreads();
    }

    #pragma unroll
    for (int i = 0; i < 4; i++) {
        float ri = red[ty * 4 + i];
        float4 o;
        o.x = oacc[i][0] * ri;
        o.y = oacc[i][1] * ri;
        o.z = oacc[i][2] * ri;
        o.w = oacc[i][3] * ri;
        *(float4*)&o_out[((size_t)(b * NS + q0 + ty * 4 + i)) * ND + tx * 4] = o;
    }
}

// ---------------------------------------------------------------------------
extern "C" void kernel_launch(void* const* d_in, const int* in_sizes, int n_in,
                              void* d_out, int out_size)
{
    const float* X  = (const float*)d_in[0];
    const float* Wq = (const float*)d_in[1];
    const float* bq = (const float*)d_in[2];
    const float* Wk = (const float*)d_in[3];
    const float* bk = (const float*)d_in[4];
    const float* Wv = (const float*)d_in[5];
    const float* bv = (const float*)d_in[6];

    float* out   = (float*)d_out;                       // [32,1024,128]
    float* probs = out + (size_t)NB * NS * ND;          // [32,1024,1024]

    cudaFuncSetAttribute(attn_kernel, cudaFuncAttributeMaxDynamicSharedMemorySize,
                         ATTN_SMEM_BYTES);

    qkv_kernel<<<dim3(512, 3), 256>>>(X, Wq, bq, Wk, bk, Wv, bv);
    attn_kernel<<<dim3(32, 32), 256, ATTN_SMEM_BYTES>>>(out, probs);
}

// round 3
// speedup vs baseline: 1.3996x; 1.3996x over previous
#include <cuda_runtime.h>
#include <cuda_bf16.h>
#include <cstdint>
#include <math.h>

#define NB 32
#define NS 1024
#define NH 1024
#define ND 128

// persistent scratch (__device__ globals per allocation rules)
__device__ float g_q[NB * NS * ND];
__device__ float g_k[NB * NS * ND];
__device__ float g_v[NB * NS * ND];
__device__ __nv_bfloat16 g_wthi[3 * ND * NH];   // [w][n][k]  (W transposed, hi part)
__device__ __nv_bfloat16 g_wtlo[3 * ND * NH];   // [w][n][k]  (lo part)

// ---------------------------------------------------------------------------
// helpers: ldmatrix + mma.sync (baseline PTX, legal on compute_103)
// ---------------------------------------------------------------------------
__device__ __forceinline__ uint32_t smem_u32(const void* p) {
    uint32_t a;
    asm("{ .reg .u64 t; cvta.to.shared.u64 t, %1; cvt.u32.u64 %0, t; }" : "=r"(a) : "l"(p));
    return a;
}
__device__ __forceinline__ void ldsm_x4(uint32_t* r, uint32_t addr) {
    asm volatile("ldmatrix.sync.aligned.m8n8.x4.shared.b16 {%0,%1,%2,%3}, [%4];"
                 : "=r"(r[0]), "=r"(r[1]), "=r"(r[2]), "=r"(r[3]) : "r"(addr));
}
__device__ __forceinline__ void ldsm_x2(uint32_t* r, uint32_t addr) {
    asm volatile("ldmatrix.sync.aligned.m8n8.x2.shared.b16 {%0,%1}, [%2];"
                 : "=r"(r[0]), "=r"(r[1]) : "r"(addr));
}
__device__ __forceinline__ void mma16816(float* d, const uint32_t* a, const uint32_t* b) {
    asm volatile(
        "mma.sync.aligned.m16n8k16.row.col.f32.bf16.bf16.f32 "
        "{%0,%1,%2,%3}, {%4,%5,%6,%7}, {%8,%9}, {%0,%1,%2,%3};"
        : "+f"(d[0]), "+f"(d[1]), "+f"(d[2]), "+f"(d[3])
        : "r"(a[0]), "r"(a[1]), "r"(a[2]), "r"(a[3]), "r"(b[0]), "r"(b[1]));
}

// ---------------------------------------------------------------------------
// Weight transpose+split: Wt[w][n][k] = split_bf16(W_w[k][n])
// ---------------------------------------------------------------------------
__global__ __launch_bounds__(256) void convw_kernel(
    const float* __restrict__ Wq, const float* __restrict__ Wk, const float* __restrict__ Wv)
{
    __shared__ float sW[64 * 129];
    int w = blockIdx.x >> 4;
    int k0 = (blockIdx.x & 15) * 64;
    const float* W = (w == 0) ? Wq : (w == 1) ? Wk : Wv;
    int tid = threadIdx.x;

    #pragma unroll
    for (int it = 0; it < 32; it++) {
        int f = tid + it * 256;
        int kk = f >> 7, n = f & 127;
        sW[kk * 129 + n] = W[(size_t)(k0 + kk) * ND + n];
    }
    __syncthreads();

    #pragma unroll
    for (int it = 0; it < 32; it++) {
        int f = tid + it * 256;
        int n = f >> 6, kk = f & 63;
        float x = sW[kk * 129 + n];
        __nv_bfloat16 hi = __float2bfloat16(x);
        __nv_bfloat16 lo = __float2bfloat16(x - __bfloat162float(hi));
        size_t di = (size_t)w * ND * NH + (size_t)n * NH + k0 + kk;
        g_wthi[di] = hi;
        g_wtlo[di] = lo;
    }
}

// ---------------------------------------------------------------------------
// QKV GEMM via mma.sync bf16 split: grid(256, 3), 256 threads.
// BM=128, BN=128, BK=32. 8 warps in 4(M)x2(N); warp tile 32x64.
// smem: Ahi/Alo [128][40] bf16, Bhi/Blo [128][40] bf16 (pad 32->40)
// ---------------------------------------------------------------------------
#define ASTRIDE 40

__global__ __launch_bounds__(256) void qkv_mma_kernel(
    const float* __restrict__ X,
    const float* __restrict__ bq, const float* __restrict__ bk, const float* __restrict__ bv)
{
    __shared__ __nv_bfloat16 sAhi[128 * ASTRIDE];
    __shared__ __nv_bfloat16 sAlo[128 * ASTRIDE];
    __shared__ __nv_bfloat16 sBhi[128 * ASTRIDE];
    __shared__ __nv_bfloat16 sBlo[128 * ASTRIDE];

    const int tid = threadIdx.x;
    const int wid = tid >> 5, lid = tid & 31;
    const int m0 = blockIdx.x * 128;
    const int w  = blockIdx.y;

    const __nv_bfloat16* Whi = g_wthi + (size_t)w * ND * NH;
    const __nv_bfloat16* Wlo = g_wtlo + (size_t)w * ND * NH;
    const float* bias = (w == 0) ? bq : (w == 1) ? bk : bv;
    float* out = (w == 0) ? g_q : (w == 1) ? g_k : g_v;

    const int warpM = (wid >> 1) * 32;   // 0,32,64,96
    const int warpN = (wid & 1) * 64;    // 0,64

    // ldmatrix lane address components
    const int a_row  = (lid & 7) + ((lid >> 3) & 1) * 8;   // 0..15
    const int a_koff = (lid >> 4) * 8;                     // 0 or 8
    const int b_row  = lid & 7;
    const int b_koff = ((lid >> 3) & 1) * 8;

    const uint32_t uAhi = smem_u32(sAhi);
    const uint32_t uAlo = smem_u32(sAlo);
    const uint32_t uBhi = smem_u32(sBhi);
    const uint32_t uBlo = smem_u32(sBlo);

    float acc[2][8][4];
    #pragma unroll
    for (int i = 0; i < 2; i++)
        #pragma unroll
        for (int j = 0; j < 8; j++)
            #pragma unroll
            for (int c = 0; c < 4; c++) acc[i][j][c] = 0.f;

    for (int kc = 0; kc < NH / 32; kc++) {
        const int k0 = kc * 32;

        // ---- stage A: X fp32 -> hi/lo bf16 ----
        #pragma unroll
        for (int it = 0; it < 4; it++) {
            int f = tid + it * 256;          // 0..1023 float4 units
            int row = f >> 3, u = f & 7;
            float4 v = *(const float4*)&X[(size_t)(m0 + row) * NH + k0 + u * 4];
            __nv_bfloat16 h0 = __float2bfloat16(v.x);
            __nv_bfloat16 h1 = __float2bfloat16(v.y);
            __nv_bfloat16 h2 = __float2bfloat16(v.z);
            __nv_bfloat16 h3 = __float2bfloat16(v.w);
            __nv_bfloat16 l0 = __float2bfloat16(v.x - __bfloat162float(h0));
            __nv_bfloat16 l1 = __float2bfloat16(v.y - __bfloat162float(h1));
            __nv_bfloat16 l2 = __float2bfloat16(v.z - __bfloat162float(h2));
            __nv_bfloat16 l3 = __float2bfloat16(v.w - __bfloat162float(h3));
            uint2 hp, lp;
            hp.x = (uint32_t)__bfloat16_as_ushort(h0) | ((uint32_t)__bfloat16_as_ushort(h1) << 16);
            hp.y = (uint32_t)__bfloat16_as_ushort(h2) | ((uint32_t)__bfloat16_as_ushort(h3) << 16);
            lp.x = (uint32_t)__bfloat16_as_ushort(l0) | ((uint32_t)__bfloat16_as_ushort(l1) << 16);
            lp.y = (uint32_t)__bfloat16_as_ushort(l2) | ((uint32_t)__bfloat16_as_ushort(l3) << 16);
            *(uint2*)&sAhi[row * ASTRIDE + u * 4] = hp;
            *(uint2*)&sAlo[row * ASTRIDE + u * 4] = lp;
        }
        // ---- stage B: pre-split weights (L2-resident) ----
        #pragma unroll
        for (int it = 0; it < 2; it++) {
            int f = tid + it * 256;          // 0..511 uint4 units
            int row = f >> 2, u = f & 3;
            uint4 vh = *(const uint4*)&Whi[(size_t)row * NH + k0 + u * 8];
            uint4 vl = *(const uint4*)&Wlo[(size_t)row * NH + k0 + u * 8];
            *(uint4*)&sBhi[row * ASTRIDE + u * 8] = vh;
            *(uint4*)&sBlo[row * ASTRIDE + u * 8] = vl;
        }
        __syncthreads();

        // ---- compute: 2 k16 steps ----
        #pragma unroll
        for (int ks = 0; ks < 2; ks++) {
            uint32_t ahi[2][4], alo[2][4];
            #pragma unroll
            for (int mi = 0; mi < 2; mi++) {
                uint32_t off = ((warpM + mi * 16 + a_row) * ASTRIDE + ks * 16 + a_koff) * 2;
                ldsm_x4(ahi[mi], uAhi + off);
                ldsm_x4(alo[mi], uAlo + off);
            }
            #pragma unroll
            for (int nj = 0; nj < 8; nj++) {
                uint32_t boff = ((warpN + nj * 8 + b_row) * ASTRIDE + ks * 16 + b_koff) * 2;
                uint32_t bhi[2], blo[2];
                ldsm_x2(bhi, uBhi + boff);
                ldsm_x2(blo, uBlo + boff);
                #pragma unroll
                for (int mi = 0; mi < 2; mi++) {
                    mma16816(acc[mi][nj], ahi[mi], bhi);
                    mma16816(acc[mi][nj], ahi[mi], blo);
                    mma16816(acc[mi][nj], alo[mi], bhi);
                }
            }
        }
        __syncthreads();
    }

    // ---- epilogue: bias add, fp32 stores ----
    #pragma unroll
    for (int mi = 0; mi < 2; mi++) {
        #pragma unroll
        for (int nj = 0; nj < 8; nj++) {
            int r0 = m0 + warpM + mi * 16 + (lid >> 2);
            int c0 = warpN + nj * 8 + (lid & 3) * 2;
            float b0 = bias[c0], b1 = bias[c0 + 1];
            float2 d01, d23;
            d01.x = acc[mi][nj][0] + b0;
            d01.y = acc[mi][nj][1] + b1;
            d23.x = acc[mi][nj][2] + b0;
            d23.y = acc[mi][nj][3] + b1;
            *(float2*)&out[(size_t)r0 * ND + c0]       = d01;
            *(float2*)&out[(size_t)(r0 + 8) * ND + c0] = d23;
        }
    }
}

// ---------------------------------------------------------------------------
// Attention: per CTA = (batch b, 32-query tile), 512 threads (16 warps).
// smem: Qs[32][128] + KV[128][129] + Ss[32][1032] + red[32]  (~215KB)
// ---------------------------------------------------------------------------
#define SS_STRIDE 1032
#define ATTN_SMEM_FLOATS (32 * 128 + 128 * 129 + 32 * SS_STRIDE + 32)
#define ATTN_SMEM_BYTES  (ATTN_SMEM_FLOATS * 4)

__global__ __launch_bounds__(512) void attn_kernel(float* __restrict__ o_out,
                                                   float* __restrict__ o_probs)
{
    extern __shared__ float smf[];
    float* Qs  = smf;
    float* KV  = Qs + 32 * 128;
    float* Ss  = KV + 128 * 129;
    float* red = Ss + 32 * SS_STRIDE;

    const int t  = threadIdx.x;
    const int b  = blockIdx.y;
    const int q0 = blockIdx.x * 32;
    const float scale = 0.08838834764831845f;  // 1/sqrt(128)

    // ---- load Q tile (pre-scaled): 1024 float4 ----
    #pragma unroll
    for (int it = 0; it < 2; it++) {
        int f  = t + it * 512;
        int rr = f >> 5;
        int c4 = (f & 31) * 4;
        float4 v = *(const float4*)&g_q[((size_t)(b * NS + q0 + rr)) * ND + c4];
        v.x *= scale; v.y *= scale; v.z *= scale; v.w *= scale;
        *(float4*)&Qs[rr * 128 + c4] = v;
    }

    const int ty = t >> 5;   // 0..15
    const int tx = t & 31;   // 0..31

    // ---- phase 1: scores S = Q @ K^T ----
    for (int kc = 0; kc < 8; kc++) {
        #pragma unroll
        for (int it = 0; it < 8; it++) {
            int f   = t + it * 512;
            int key = f >> 5;
            int d4  = (f & 31) * 4;
            float4 v = *(const float4*)&g_k[((size_t)(b * NS + kc * 128 + key)) * ND + d4];
            float* dst = &KV[key * 129 + d4];
            dst[0] = v.x; dst[1] = v.y; dst[2] = v.z; dst[3] = v.w;
        }
        __syncthreads();

        float acc[2][4];
        #pragma unroll
        for (int i = 0; i < 2; i++)
            #pragma unroll
            for (int j = 0; j < 4; j++) acc[i][j] = 0.f;

        #pragma unroll 4
        for (int kk = 0; kk < 128; kk++) {
            float qv[2], kv4[4];
            #pragma unroll
            for (int i = 0; i < 2; i++) qv[i] = Qs[(ty * 2 + i) * 128 + kk];
            #pragma unroll
            for (int j = 0; j < 4; j++) kv4[j] = KV[(tx + 32 * j) * 129 + kk];
            #pragma unroll
            for (int i = 0; i < 2; i++)
                #pragma unroll
                for (int j = 0; j < 4; j++)
                    acc[i][j] += qv[i] * kv4[j];
        }
        #pragma unroll
        for (int i = 0; i < 2; i++)
            #pragma unroll
            for (int j = 0; j < 4; j++)
                Ss[(ty * 2 + i) * SS_STRIDE + kc * 128 + tx + 32 * j] = acc[i][j];
        __syncthreads();
    }

    // ---- softmax: 16 threads per row ----
    {
        int rr = t >> 4;       // 0..31
        int j  = t & 15;
        float* row = &Ss[rr * SS_STRIDE];
        float mx = -1e30f;
        #pragma unroll 8
        for (int tt = 0; tt < 64; tt++) mx = fmaxf(mx, row[j + 16 * tt]);
        #pragma unroll
        for (int o = 1; o < 16; o <<= 1) mx = fmaxf(mx, __shfl_xor_sync(0xffffffffu, mx, o));
        float sum = 0.f;
        #pragma unroll 8
        for (int tt = 0; tt < 64; tt++) {
            int idx = j + 16 * tt;
            float e = __expf(row[idx] - mx);
            row[idx] = e;
            sum += e;
        }
        #pragma unroll
        for (int o = 1; o < 16; o <<= 1) sum += __shfl_xor_sync(0xffffffffu, sum, o);
        if (j == 0) red[rr] = 1.f / sum;
    }
    __syncthreads();

    // ---- coalesced probs write: 8192 float4 ----
    #pragma unroll 4
    for (int it = 0; it < 16; it++) {
        int f  = t + it * 512;
        int rr = f >> 8;
        int c4 = (f & 255) * 4;
        float ri = red[rr];
        float4 e = *(const float4*)&Ss[rr * SS_STRIDE + c4];
        e.x *= ri; e.y *= ri; e.z *= ri; e.w *= ri;
        *(float4*)&o_probs[((size_t)(b * NS + q0 + rr)) * NS + c4] = e;
    }
    __syncthreads();

    // ---- phase 3: O = (exp-S @ V) * 1/sum ----
    float oacc[2][4];
    #pragma unroll
    for (int i = 0; i < 2; i++)
        #pragma unroll
        for (int j = 0; j < 4; j++) oacc[i][j] = 0.f;

    for (int vc = 0; vc < 8; vc++) {
        #pragma unroll
        for (int it = 0; it < 8; it++) {
            int f  = t + it * 512;
            int kv = f >> 5;
            int d4 = (f & 31) * 4;
            float4 v = *(const float4*)&g_v[((size_t)(b * NS + vc * 128 + kv)) * ND + d4];
            *(float4*)&KV[kv * 128 + d4] = v;
        }
        __syncthreads();

        #pragma unroll 4
        for (int kv = 0; kv < 128; kv++) {
            float4 vv = *(const float4*)&KV[kv * 128 + tx * 4];
            #pragma unroll
            for (int i = 0; i < 2; i++) {
                float p = Ss[(ty * 2 + i) * SS_STRIDE + vc * 128 + kv];
                oacc[i][0] += p * vv.x;
                oacc[i][1] += p * vv.y;
                oacc[i][2] += p * vv.z;
                oacc[i][3] += p * vv.w;
            }
        }
        __syncthreads();
    }

    #pragma unroll
    for (int i = 0; i < 2; i++) {
        float ri = red[ty * 2 + i];
        float4 o;
        o.x = oacc[i][0] * ri;
        o.y = oacc[i][1] * ri;
        o.z = oacc[i][2] * ri;
        o.w = oacc[i][3] * ri;
        *(float4*)&o_out[((size_t)(b * NS + q0 + ty * 2 + i)) * ND + tx * 4] = o;
    }
}

// ---------------------------------------------------------------------------
extern "C" void kernel_launch(void* const* d_in, const int* in_sizes, int n_in,
                              void* d_out, int out_size)
{
    const float* X  = (const float*)d_in[0];
    const float* Wq = (const float*)d_in[1];
    const float* bq = (const float*)d_in[2];
    const float* Wk = (const float*)d_in[3];
    const float* bk = (const float*)d_in[4];
    const float* Wv = (const float*)d_in[5];
    const float* bv = (const float*)d_in[6];

    float* out   = (float*)d_out;                 // [32,1024,128]
    float* probs = out + (size_t)NB * NS * ND;    // [32,1024,1024]

    cudaFuncSetAttribute(attn_kernel, cudaFuncAttributeMaxDynamicSharedMemorySize,
                         ATTN_SMEM_BYTES);

    convw_kernel<<<48, 256>>>(Wq, Wk, Wv);
    qkv_mma_kernel<<<dim3(256, 3), 256>>>(X, bq, bk, bv);
    attn_kernel<<<dim3(32, 32), 512, ATTN_SMEM_BYTES>>>(out, probs);
}

// round 4
// speedup vs baseline: 2.1966x; 1.5694x over previous
#include <cuda_runtime.h>
#include <cuda_bf16.h>
#include <cstdint>
#include <math.h>

#define NB 32
#define NS 1024
#define NH 1024
#define ND 128

// persistent scratch (__device__ globals per allocation rules) — split bf16
__device__ __nv_bfloat16 g_qh[NB * NS * ND];
__device__ __nv_bfloat16 g_ql[NB * NS * ND];
__device__ __nv_bfloat16 g_kh[NB * NS * ND];
__device__ __nv_bfloat16 g_kl[NB * NS * ND];
__device__ __nv_bfloat16 g_vh[NB * NS * ND];
__device__ __nv_bfloat16 g_vl[NB * NS * ND];
__device__ __nv_bfloat16 g_wthi[3 * ND * NH];   // [w][n][k]  (W transposed, hi)
__device__ __nv_bfloat16 g_wtlo[3 * ND * NH];   // [w][n][k]  (lo)

// ---------------------------------------------------------------------------
// helpers
// ---------------------------------------------------------------------------
__device__ __forceinline__ uint32_t smem_u32(const void* p) {
    uint32_t a;
    asm("{ .reg .u64 t; cvta.to.shared.u64 t, %1; cvt.u32.u64 %0, t; }" : "=r"(a) : "l"(p));
    return a;
}
__device__ __forceinline__ void ldsm_x4(uint32_t* r, uint32_t addr) {
    asm volatile("ldmatrix.sync.aligned.m8n8.x4.shared.b16 {%0,%1,%2,%3}, [%4];"
                 : "=r"(r[0]), "=r"(r[1]), "=r"(r[2]), "=r"(r[3]) : "r"(addr));
}
__device__ __forceinline__ void ldsm_x4_t(uint32_t* r, uint32_t addr) {
    asm volatile("ldmatrix.sync.aligned.m8n8.x4.trans.shared.b16 {%0,%1,%2,%3}, [%4];"
                 : "=r"(r[0]), "=r"(r[1]), "=r"(r[2]), "=r"(r[3]) : "r"(addr));
}
__device__ __forceinline__ void mma16816(float* d, const uint32_t* a, const uint32_t* b) {
    asm volatile(
        "mma.sync.aligned.m16n8k16.row.col.f32.bf16.bf16.f32 "
        "{%0,%1,%2,%3}, {%4,%5,%6,%7}, {%8,%9}, {%0,%1,%2,%3};"
        : "+f"(d[0]), "+f"(d[1]), "+f"(d[2]), "+f"(d[3])
        : "r"(a[0]), "r"(a[1]), "r"(a[2]), "r"(a[3]), "r"(b[0]), "r"(b[1]));
}
__device__ __forceinline__ void split2(float a, float b, uint32_t& hi, uint32_t& lo) {
    __nv_bfloat16 ha = __float2bfloat16(a), hb = __float2bfloat16(b);
    __nv_bfloat16 la = __float2bfloat16(a - __bfloat162float(ha));
    __nv_bfloat16 lb = __float2bfloat16(b - __bfloat162float(hb));
    hi = (uint32_t)__bfloat16_as_ushort(ha) | ((uint32_t)__bfloat16_as_ushort(hb) << 16);
    lo = (uint32_t)__bfloat16_as_ushort(la) | ((uint32_t)__bfloat16_as_ushort(lb) << 16);
}
// fast exp: deg-5 Taylor on centered frac + exponent bit-insert (no MUFU), ~2e-6 rel
__device__ __forceinline__ float fast_exp(float x) {
    float t = x * 1.4426950408889634f;
    int ii = __float2int_rn(t);
    float f = t - (float)ii;
    float y = f * 0.6931471805599453f;
    float p = 1.0f + y * (1.0f + y * (0.5f + y * (0.16666667f + y * (0.041666668f + y * 0.008333334f))));
    return __int_as_float(__float_as_int(p) + (ii << 23));
}

// ---------------------------------------------------------------------------
// Weight transpose+split: Wt[w][n][k] = split_bf16(W_w[k][n])
// ---------------------------------------------------------------------------
__global__ __launch_bounds__(256) void convw_kernel(
    const float* __restrict__ Wq, const float* __restrict__ Wk, const float* __restrict__ Wv)
{
    __shared__ float sW[64 * 129];
    int w = blockIdx.x >> 4;
    int k0 = (blockIdx.x & 15) * 64;
    const float* W = (w == 0) ? Wq : (w == 1) ? Wk : Wv;
    int tid = threadIdx.x;

    #pragma unroll
    for (int it = 0; it < 32; it++) {
        int f = tid + it * 256;
        int kk = f >> 7, n = f & 127;
        sW[kk * 129 + n] = W[(size_t)(k0 + kk) * ND + n];
    }
    __syncthreads();

    #pragma unroll
    for (int it = 0; it < 32; it++) {
        int f = tid + it * 256;
        int n = f >> 6, kk = f & 63;
        float x = sW[kk * 129 + n];
        __nv_bfloat16 hi = __float2bfloat16(x);
        __nv_bfloat16 lo = __float2bfloat16(x - __bfloat162float(hi));
        size_t di = (size_t)w * ND * NH + (size_t)n * NH + k0 + kk;
        g_wthi[di] = hi;
        g_wtlo[di] = lo;
    }
}

// ---------------------------------------------------------------------------
// QKV GEMM via mma.sync bf16 split: grid(256, 3), 256 threads.
// BM=128, BN=128, BK=32. 8 warps in 4(M)x2(N); warp tile 32x64.
// Epilogue writes split-bf16 q (pre-scaled), k, v.
// ---------------------------------------------------------------------------
#define ASTRIDE 40

__global__ __launch_bounds__(256) void qkv_mma_kernel(
    const float* __restrict__ X,
    const float* __restrict__ bq, const float* __restrict__ bk, const float* __restrict__ bv)
{
    __shared__ __nv_bfloat16 sAhi[128 * ASTRIDE];
    __shared__ __nv_bfloat16 sAlo[128 * ASTRIDE];
    __shared__ __nv_bfloat16 sBhi[128 * ASTRIDE];
    __shared__ __nv_bfloat16 sBlo[128 * ASTRIDE];

    const int tid = threadIdx.x;
    const int wid = tid >> 5, lid = tid & 31;
    const int m0 = blockIdx.x * 128;
    const int w  = blockIdx.y;

    const __nv_bfloat16* Whi = g_wthi + (size_t)w * ND * NH;
    const __nv_bfloat16* Wlo = g_wtlo + (size_t)w * ND * NH;
    const float* bias = (w == 0) ? bq : (w == 1) ? bk : bv;
    __nv_bfloat16* outh = (w == 0) ? g_qh : (w == 1) ? g_kh : g_vh;
    __nv_bfloat16* outl = (w == 0) ? g_ql : (w == 1) ? g_kl : g_vl;
    const float oscale = (w == 0) ? 0.08838834764831845f : 1.0f;

    const int warpM = (wid >> 1) * 32;   // 0,32,64,96
    const int warpN = (wid & 1) * 64;    // 0,64

    const int a_row  = lid & 15;
    const int a_koff = (lid >> 4) * 8;
    const int bx_row  = (lid & 7) + (lid >> 4) * 8;
    const int bx_koff = ((lid >> 3) & 1) * 8;

    const uint32_t uAhi = smem_u32(sAhi);
    const uint32_t uAlo = smem_u32(sAlo);
    const uint32_t uBhi = smem_u32(sBhi);
    const uint32_t uBlo = smem_u32(sBlo);

    float acc[2][8][4];
    #pragma unroll
    for (int i = 0; i < 2; i++)
        #pragma unroll
        for (int j = 0; j < 8; j++)
            #pragma unroll
            for (int c = 0; c < 4; c++) acc[i][j][c] = 0.f;

    for (int kc = 0; kc < NH / 32; kc++) {
        const int k0 = kc * 32;

        // stage A: X fp32 -> hi/lo bf16
        #pragma unroll
        for (int it = 0; it < 4; it++) {
            int f = tid + it * 256;
            int row = f >> 3, u = f & 7;
            float4 v = *(const float4*)&X[(size_t)(m0 + row) * NH + k0 + u * 4];
            uint2 hp, lp;
            split2(v.x, v.y, hp.x, lp.x);
            split2(v.z, v.w, hp.y, lp.y);
            *(uint2*)&sAhi[row * ASTRIDE + u * 4] = hp;
            *(uint2*)&sAlo[row * ASTRIDE + u * 4] = lp;
        }
        // stage B
        #pragma unroll
        for (int it = 0; it < 2; it++) {
            int f = tid + it * 256;
            int row = f >> 2, u = f & 3;
            uint4 vh = *(const uint4*)&Whi[(size_t)row * NH + k0 + u * 8];
            uint4 vl = *(const uint4*)&Wlo[(size_t)row * NH + k0 + u * 8];
            *(uint4*)&sBhi[row * ASTRIDE + u * 8] = vh;
            *(uint4*)&sBlo[row * ASTRIDE + u * 8] = vl;
        }
        __syncthreads();

        #pragma unroll
        for (int ks = 0; ks < 2; ks++) {
            uint32_t ahi[2][4], alo[2][4];
            #pragma unroll
            for (int mi = 0; mi < 2; mi++) {
                uint32_t off = ((warpM + mi * 16 + a_row) * ASTRIDE + ks * 16 + a_koff) * 2;
                ldsm_x4(ahi[mi], uAhi + off);
                ldsm_x4(alo[mi], uAlo + off);
            }
            #pragma unroll
            for (int njp = 0; njp < 4; njp++) {
                uint32_t boff = ((warpN + njp * 16 + bx_row) * ASTRIDE + ks * 16 + bx_koff) * 2;
                uint32_t bh[4], bl[4];
                ldsm_x4(bh, uBhi + boff);
                ldsm_x4(bl, uBlo + boff);
                #pragma unroll
                for (int h = 0; h < 2; h++) {
                    #pragma unroll
                    for (int mi = 0; mi < 2; mi++) {
                        mma16816(acc[mi][njp * 2 + h], ahi[mi], &bh[h * 2]);
                        mma16816(acc[mi][njp * 2 + h], ahi[mi], &bl[h * 2]);
                        mma16816(acc[mi][njp * 2 + h], alo[mi], &bh[h * 2]);
                    }
                }
            }
        }
        __syncthreads();
    }

    // epilogue: bias add, (q: scale), split-bf16 stores
    #pragma unroll
    for (int mi = 0; mi < 2; mi++) {
        #pragma unroll
        for (int nj = 0; nj < 8; nj++) {
            int r0 = m0 + warpM + mi * 16 + (lid >> 2);
            int c0 = warpN + nj * 8 + (lid & 3) * 2;
            float b0 = bias[c0], b1 = bias[c0 + 1];
            float v0 = (acc[mi][nj][0] + b0) * oscale;
            float v1 = (acc[mi][nj][1] + b1) * oscale;
            float v2 = (acc[mi][nj][2] + b0) * oscale;
            float v3 = (acc[mi][nj][3] + b1) * oscale;
            uint32_t h01, l01, h23, l23;
            split2(v0, v1, h01, l01);
            split2(v2, v3, h23, l23);
            *(uint32_t*)&outh[(size_t)r0 * ND + c0] = h01;
            *(uint32_t*)&outl[(size_t)r0 * ND + c0] = l01;
            *(uint32_t*)&outh[(size_t)(r0 + 8) * ND + c0] = h23;
            *(uint32_t*)&outl[(size_t)(r0 + 8) * ND + c0] = l23;
        }
    }
}

// ---------------------------------------------------------------------------
// Attention via mma.sync: per CTA = (batch b, 32-query tile), 256 threads.
// smem: sQh/sQl 32x136 bf16 (reused as P), sKh/sKl 128x136 bf16 (K then V),
//       Ss 32x1032 fp32, red[32]. Total 219264 bytes.
// 8 warps: warp w = full M32 x 16-col slice (keys in phase S, dims in phase PV)
// ---------------------------------------------------------------------------
#define QSTRIDE 136
#define SS_STRIDE 1032
#define OFF_QH 0
#define OFF_QL (32 * QSTRIDE * 2)                 // 8704
#define OFF_KH (OFF_QL + 32 * QSTRIDE * 2)        // 17408
#define OFF_KL (OFF_KH + 128 * QSTRIDE * 2)       // 52224
#define OFF_SS (OFF_KL + 128 * QSTRIDE * 2)       // 87040
#define OFF_RED (OFF_SS + 32 * SS_STRIDE * 4)     // 219136
#define ATTN_SMEM_BYTES (OFF_RED + 128)           // 219264

__global__ __launch_bounds__(256) void attn_kernel(float* __restrict__ o_out,
                                                   float* __restrict__ o_probs)
{
    extern __shared__ char smem[];
    __nv_bfloat16* sQh = (__nv_bfloat16*)(smem + OFF_QH);
    __nv_bfloat16* sQl = (__nv_bfloat16*)(smem + OFF_QL);
    __nv_bfloat16* sKh = (__nv_bfloat16*)(smem + OFF_KH);
    __nv_bfloat16* sKl = (__nv_bfloat16*)(smem + OFF_KL);
    float* Ss  = (float*)(smem + OFF_SS);
    float* red = (float*)(smem + OFF_RED);

    const uint32_t uQh = smem_u32(sQh), uQl = smem_u32(sQl);
    const uint32_t uKh = smem_u32(sKh), uKl = smem_u32(sKl);

    const int tid = threadIdx.x;
    const int wid = tid >> 5, lid = tid & 31;
    const int b  = blockIdx.y;
    const int q0 = blockIdx.x * 32;

    const int a_row  = lid & 15;
    const int a_koff = (lid >> 4) * 8;
    const int bx_row  = (lid & 7) + (lid >> 4) * 8;
    const int bx_koff = ((lid >> 3) & 1) * 8;
    // trans-ldsm (V^T) address components
    const int t_krow = (lid & 7) + ((lid >> 3) & 1) * 8;
    const int t_ncol = (lid >> 4) * 8;

    // ---- stage Q (pre-scaled split bf16 from qkv) ----
    #pragma unroll
    for (int it = 0; it < 4; it++) {
        int f = tid + it * 256;              // 0..1023
        int arr = f >> 9, g = f & 511;
        int row = g >> 4, u = g & 15;
        const __nv_bfloat16* src = (arr ? g_ql : g_qh) + ((size_t)(b * NS + q0 + row)) * ND + u * 8;
        __nv_bfloat16* dst = (arr ? sQl : sQh) + row * QSTRIDE + u * 8;
        *(uint4*)dst = *(const uint4*)src;
    }

    // ================= phase 1: S = Q @ K^T =================
    for (int kc = 0; kc < 8; kc++) {
        __syncthreads();
        #pragma unroll
        for (int it = 0; it < 16; it++) {
            int f = tid + it * 256;          // 0..4095
            int arr = f >> 11, g = f & 2047;
            int row = g >> 4, u = g & 15;
            const __nv_bfloat16* src = (arr ? g_kl : g_kh) + ((size_t)(b * NS + kc * 128 + row)) * ND + u * 8;
            __nv_bfloat16* dst = (arr ? sKl : sKh) + row * QSTRIDE + u * 8;
            *(uint4*)dst = *(const uint4*)src;
        }
        __syncthreads();

        float acc[2][2][4];
        #pragma unroll
        for (int mi = 0; mi < 2; mi++)
            #pragma unroll
            for (int nt = 0; nt < 2; nt++)
                #pragma unroll
                for (int c = 0; c < 4; c++) acc[mi][nt][c] = 0.f;

        #pragma unroll
        for (int ks = 0; ks < 8; ks++) {
            uint32_t ah[2][4], al[2][4];
            #pragma unroll
            for (int mi = 0; mi < 2; mi++) {
                uint32_t off = ((mi * 16 + a_row) * QSTRIDE + ks * 16 + a_koff) * 2;
                ldsm_x4(ah[mi], uQh + off);
                ldsm_x4(al[mi], uQl + off);
            }
            uint32_t boff = ((wid * 16 + bx_row) * QSTRIDE + ks * 16 + bx_koff) * 2;
            uint32_t bh[4], bl[4];
            ldsm_x4(bh, uKh + boff);
            ldsm_x4(bl, uKl + boff);
            #pragma unroll
            for (int nt = 0; nt < 2; nt++) {
                #pragma unroll
                for (int mi = 0; mi < 2; mi++) {
                    mma16816(acc[mi][nt], ah[mi], &bh[nt * 2]);
                    mma16816(acc[mi][nt], ah[mi], &bl[nt * 2]);
                    mma16816(acc[mi][nt], al[mi], &bh[nt * 2]);
                }
            }
        }
        // store S chunk fp32
        #pragma unroll
        for (int mi = 0; mi < 2; mi++) {
            #pragma unroll
            for (int nt = 0; nt < 2; nt++) {
                int row0 = mi * 16 + (lid >> 2);
                int col  = kc * 128 + wid * 16 + nt * 8 + (lid & 3) * 2;
                *(float2*)&Ss[row0 * SS_STRIDE + col] = make_float2(acc[mi][nt][0], acc[mi][nt][1]);
                *(float2*)&Ss[(row0 + 8) * SS_STRIDE + col] = make_float2(acc[mi][nt][2], acc[mi][nt][3]);
            }
        }
    }
    __syncthreads();

    // ================= softmax (8 threads/row, poly exp) =================
    {
        int rr = tid >> 3;
        int j  = tid & 7;
        float* row = &Ss[rr * SS_STRIDE];
        float mx = -1e30f;
        #pragma unroll 8
        for (int tt = 0; tt < 128; tt++) mx = fmaxf(mx, row[j + 8 * tt]);
        #pragma unroll
        for (int o = 1; o < 8; o <<= 1) mx = fmaxf(mx, __shfl_xor_sync(0xffffffffu, mx, o));
        float sum = 0.f;
        #pragma unroll 8
        for (int tt = 0; tt < 128; tt++) {
            int idx = j + 8 * tt;
            float e = fast_exp(row[idx] - mx);
            row[idx] = e;
            sum += e;
        }
        #pragma unroll
        for (int o = 1; o < 8; o <<= 1) sum += __shfl_xor_sync(0xffffffffu, sum, o);
        if (j == 0) red[rr] = 1.f / sum;
    }
    __syncthreads();

    // ================= probs write (normalized) =================
    #pragma unroll 4
    for (int it = 0; it < 32; it++) {
        int f  = tid + it * 256;             // 0..8191 float4 units
        int rr = f >> 8;
        int c4 = (f & 255) * 4;
        float ri = red[rr];
        float4 e = *(const float4*)&Ss[rr * SS_STRIDE + c4];
        e.x *= ri; e.y *= ri; e.z *= ri; e.w *= ri;
        *(float4*)&o_probs[((size_t)(b * NS + q0 + rr)) * NS + c4] = e;
    }

    // ================= phase 3: O = (E @ V) * 1/sum =================
    float acc2[2][2][4];
    #pragma unroll
    for (int mi = 0; mi < 2; mi++)
        #pragma unroll
        for (int nt = 0; nt < 2; nt++)
            #pragma unroll
            for (int c = 0; c < 4; c++) acc2[mi][nt][c] = 0.f;

    for (int vc = 0; vc < 8; vc++) {
        __syncthreads();
        // stage V chunk into sK buffers
        #pragma unroll
        for (int it = 0; it < 16; it++) {
            int f = tid + it * 256;
            int arr = f >> 11, g = f & 2047;
            int row = g >> 4, u = g & 15;
            const __nv_bfloat16* src = (arr ? g_vl : g_vh) + ((size_t)(b * NS + vc * 128 + row)) * ND + u * 8;
            __nv_bfloat16* dst = (arr ? sKl : sKh) + row * QSTRIDE + u * 8;
            *(uint4*)dst = *(const uint4*)src;
        }
        // convert P chunk (unnormalized e) to split bf16 into sQ buffers
        {
            int row = tid >> 3;              // 0..31
            int j   = tid & 7;               // 16 keys each
            const float* srow = &Ss[row * SS_STRIDE + vc * 128 + j * 16];
            uint4 h0, l0, h1, l1;
            float4 e0 = *(const float4*)&srow[0];
            float4 e1 = *(const float4*)&srow[4];
            float4 e2 = *(const float4*)&srow[8];
            float4 e3 = *(const float4*)&srow[12];
            split2(e0.x, e0.y, h0.x, l0.x); split2(e0.z, e0.w, h0.y, l0.y);
            split2(e1.x, e1.y, h0.z, l0.z); split2(e1.z, e1.w, h0.w, l0.w);
            split2(e2.x, e2.y, h1.x, l1.x); split2(e2.z, e2.w, h1.y, l1.y);
            split2(e3.x, e3.y, h1.z, l1.z); split2(e3.z, e3.w, h1.w, l1.w);
            *(uint4*)&sQh[row * QSTRIDE + j * 16]     = h0;
            *(uint4*)&sQh[row * QSTRIDE + j * 16 + 8] = h1;
            *(uint4*)&sQl[row * QSTRIDE + j * 16]     = l0;
            *(uint4*)&sQl[row * QSTRIDE + j * 16 + 8] = l1;
        }
        __syncthreads();

        #pragma unroll
        for (int ks = 0; ks < 8; ks++) {
            uint32_t ph[2][4], pl[2][4];
            #pragma unroll
            for (int mi = 0; mi < 2; mi++) {
                uint32_t off = ((mi * 16 + a_row) * QSTRIDE + ks * 16 + a_koff) * 2;
                ldsm_x4(ph[mi], uQh + off);
                ldsm_x4(pl[mi], uQl + off);
            }
            // V^T fragments via trans ldsm: region keys[ks*16..+15] x dims[wid*16..+15]
            uint32_t toff = ((ks * 16 + t_krow) * QSTRIDE + wid * 16 + t_ncol) * 2;
            uint32_t vh[4], vl[4];
            ldsm_x4_t(vh, uKh + toff);
            ldsm_x4_t(vl, uKl + toff);
            #pragma unroll
            for (int nt = 0; nt < 2; nt++) {
                #pragma unroll
                for (int mi = 0; mi < 2; mi++) {
                    mma16816(acc2[mi][nt], ph[mi], &vh[nt * 2]);
                    mma16816(acc2[mi][nt], ph[mi], &vl[nt * 2]);
                    mma16816(acc2[mi][nt], pl[mi], &vh[nt * 2]);
                }
            }
        }
    }

    // ---- epilogue: O = acc2 * 1/sum ----
    #pragma unroll
    for (int mi = 0; mi < 2; mi++) {
        #pragma unroll
        for (int nt = 0; nt < 2; nt++) {
            int row0 = mi * 16 + (lid >> 2);
            int col  = wid * 16 + nt * 8 + (lid & 3) * 2;
            float r1 = red[row0], r2 = red[row0 + 8];
            *(float2*)&o_out[((size_t)(b * NS + q0 + row0)) * ND + col] =
                make_float2(acc2[mi][nt][0] * r1, acc2[mi][nt][1] * r1);
            *(float2*)&o_out[((size_t)(b * NS + q0 + row0 + 8)) * ND + col] =
                make_float2(acc2[mi][nt][2] * r2, acc2[mi][nt][3] * r2);
        }
    }
}

// ---------------------------------------------------------------------------
extern "C" void kernel_launch(void* const* d_in, const int* in_sizes, int n_in,
                              void* d_out, int out_size)
{
    const float* X  = (const float*)d_in[0];
    const float* Wq = (const float*)d_in[1];
    const float* bq = (const float*)d_in[2];
    const float* Wk = (const float*)d_in[3];
    const float* bk = (const float*)d_in[4];
    const float* Wv = (const float*)d_in[5];
    const float* bv = (const float*)d_in[6];

    float* out   = (float*)d_out;                 // [32,1024,128]
    float* probs = out + (size_t)NB * NS * ND;    // [32,1024,1024]

    cudaFuncSetAttribute(attn_kernel, cudaFuncAttributeMaxDynamicSharedMemorySize,
                         ATTN_SMEM_BYTES);

    convw_kernel<<<48, 256>>>(Wq, Wk, Wv);
    qkv_mma_kernel<<<dim3(256, 3), 256>>>(X, bq, bk, bv);
    attn_kernel<<<dim3(32, 32), 256, ATTN_SMEM_BYTES>>>(out, probs);
}

// round 5
// speedup vs baseline: 2.5650x; 1.1677x over previous
#include <cuda_runtime.h>
#include <cuda_bf16.h>
#include <cstdint>
#include <math.h>

#define NB 32
#define NS 1024
#define NH 1024
#define ND 128

// persistent scratch (__device__ globals per allocation rules) — split bf16
__device__ __nv_bfloat16 g_xh[NB * NS * NH];
__device__ __nv_bfloat16 g_xl[NB * NS * NH];
__device__ __nv_bfloat16 g_qh[NB * NS * ND];
__device__ __nv_bfloat16 g_ql[NB * NS * ND];
__device__ __nv_bfloat16 g_kh[NB * NS * ND];
__device__ __nv_bfloat16 g_kl[NB * NS * ND];
__device__ __nv_bfloat16 g_vh[NB * NS * ND];
__device__ __nv_bfloat16 g_vl[NB * NS * ND];
__device__ __nv_bfloat16 g_wthi[3 * ND * NH];   // [w][n][k]
__device__ __nv_bfloat16 g_wtlo[3 * ND * NH];

// ---------------------------------------------------------------------------
// helpers
// ---------------------------------------------------------------------------
__device__ __forceinline__ uint32_t smem_u32(const void* p) {
    uint32_t a;
    asm("{ .reg .u64 t; cvta.to.shared.u64 t, %1; cvt.u32.u64 %0, t; }" : "=r"(a) : "l"(p));
    return a;
}
__device__ __forceinline__ void ldsm_x4(uint32_t* r, uint32_t addr) {
    asm volatile("ldmatrix.sync.aligned.m8n8.x4.shared.b16 {%0,%1,%2,%3}, [%4];"
                 : "=r"(r[0]), "=r"(r[1]), "=r"(r[2]), "=r"(r[3]) : "r"(addr));
}
__device__ __forceinline__ void ldsm_x2(uint32_t* r, uint32_t addr) {
    asm volatile("ldmatrix.sync.aligned.m8n8.x2.shared.b16 {%0,%1}, [%2];"
                 : "=r"(r[0]), "=r"(r[1]) : "r"(addr));
}
__device__ __forceinline__ void ldsm_x4_t(uint32_t* r, uint32_t addr) {
    asm volatile("ldmatrix.sync.aligned.m8n8.x4.trans.shared.b16 {%0,%1,%2,%3}, [%4];"
                 : "=r"(r[0]), "=r"(r[1]), "=r"(r[2]), "=r"(r[3]) : "r"(addr));
}
__device__ __forceinline__ void mma16816(float* d, const uint32_t* a, const uint32_t* b) {
    asm volatile(
        "mma.sync.aligned.m16n8k16.row.col.f32.bf16.bf16.f32 "
        "{%0,%1,%2,%3}, {%4,%5,%6,%7}, {%8,%9}, {%0,%1,%2,%3};"
        : "+f"(d[0]), "+f"(d[1]), "+f"(d[2]), "+f"(d[3])
        : "r"(a[0]), "r"(a[1]), "r"(a[2]), "r"(a[3]), "r"(b[0]), "r"(b[1]));
}
__device__ __forceinline__ void split2(float a, float b, uint32_t& hi, uint32_t& lo) {
    __nv_bfloat16 ha = __float2bfloat16(a), hb = __float2bfloat16(b);
    __nv_bfloat16 la = __float2bfloat16(a - __bfloat162float(ha));
    __nv_bfloat16 lb = __float2bfloat16(b - __bfloat162float(hb));
    hi = (uint32_t)__bfloat16_as_ushort(ha) | ((uint32_t)__bfloat16_as_ushort(hb) << 16);
    lo = (uint32_t)__bfloat16_as_ushort(la) | ((uint32_t)__bfloat16_as_ushort(lb) << 16);
}
__device__ __forceinline__ float fast_exp(float x) {
    float t = x * 1.4426950408889634f;
    int ii = __float2int_rn(t);
    float f = t - (float)ii;
    float y = f * 0.6931471805599453f;
    float p = 1.0f + y * (1.0f + y * (0.5f + y * (0.16666667f + y * (0.041666668f + y * 0.008333334f))));
    return __int_as_float(__float_as_int(p) + (ii << 23));
}
__device__ __forceinline__ void cp_async16(uint32_t smem_addr, const void* gptr) {
    asm volatile("cp.async.cg.shared.global [%0], [%1], 16;" :: "r"(smem_addr), "l"(gptr));
}
#define CP_COMMIT() asm volatile("cp.async.commit_group;" ::: "memory")
#define CP_WAIT(n)  asm volatile("cp.async.wait_group %0;" :: "n"(n) : "memory")

// ---------------------------------------------------------------------------
// X split: g_xh/g_xl = split_bf16(X)
// ---------------------------------------------------------------------------
__global__ __launch_bounds__(256) void convx_kernel(const float* __restrict__ X)
{
    const int total = NB * NS * NH / 4;   // float4 units
    for (int i = blockIdx.x * 256 + threadIdx.x; i < total; i += gridDim.x * 256) {
        float4 v = ((const float4*)X)[i];
        uint2 h, l;
        split2(v.x, v.y, h.x, l.x);
        split2(v.z, v.w, h.y, l.y);
        ((uint2*)g_xh)[i] = h;
        ((uint2*)g_xl)[i] = l;
    }
}

// ---------------------------------------------------------------------------
// Weight transpose+split: Wt[w][n][k] = split_bf16(W_w[k][n])
// ---------------------------------------------------------------------------
__global__ __launch_bounds__(256) void convw_kernel(
    const float* __restrict__ Wq, const float* __restrict__ Wk, const float* __restrict__ Wv)
{
    __shared__ float sW[64 * 129];
    int w = blockIdx.x >> 4;
    int k0 = (blockIdx.x & 15) * 64;
    const float* W = (w == 0) ? Wq : (w == 1) ? Wk : Wv;
    int tid = threadIdx.x;

    #pragma unroll
    for (int it = 0; it < 32; it++) {
        int f = tid + it * 256;
        int kk = f >> 7, n = f & 127;
        sW[kk * 129 + n] = W[(size_t)(k0 + kk) * ND + n];
    }
    __syncthreads();

    #pragma unroll
    for (int it = 0; it < 32; it++) {
        int f = tid + it * 256;
        int n = f >> 6, kk = f & 63;
        float x = sW[kk * 129 + n];
        __nv_bfloat16 hi = __float2bfloat16(x);
        __nv_bfloat16 lo = __float2bfloat16(x - __bfloat162float(hi));
        size_t di = (size_t)w * ND * NH + (size_t)n * NH + k0 + kk;
        g_wthi[di] = hi;
        g_wtlo[di] = lo;
    }
}

// ---------------------------------------------------------------------------
// QKV GEMM: mma.sync bf16 3-term split, cp.async 2-stage pipeline.
// grid(256, 3), 256 threads. BM=128, BN=128, BK=32; 8 warps 4(M)x2(N).
// ---------------------------------------------------------------------------
#define QK_ASTRIDE 40
#define QK_AHI 0
#define QK_ALO 10240
#define QK_BHI 20480
#define QK_BLO 30720
#define QK_STAGE 40960
#define QK_SMEM (2 * QK_STAGE)

__global__ __launch_bounds__(256, 1) void qkv_mma_kernel(
    const float* __restrict__ bq, const float* __restrict__ bk, const float* __restrict__ bv)
{
    extern __shared__ char sm[];
    const uint32_t uS = smem_u32(sm);

    const int tid = threadIdx.x;
    const int wid = tid >> 5, lid = tid & 31;
    const int m0 = blockIdx.x * 128;
    const int w  = blockIdx.y;

    const __nv_bfloat16* Whi = g_wthi + (size_t)w * ND * NH;
    const __nv_bfloat16* Wlo = g_wtlo + (size_t)w * ND * NH;
    const float* bias = (w == 0) ? bq : (w == 1) ? bk : bv;
    __nv_bfloat16* outh = (w == 0) ? g_qh : (w == 1) ? g_kh : g_vh;
    __nv_bfloat16* outl = (w == 0) ? g_ql : (w == 1) ? g_kl : g_vl;
    const float oscale = (w == 0) ? 0.08838834764831845f : 1.0f;

    const int warpM = (wid >> 1) * 32;
    const int warpN = (wid & 1) * 64;

    const int a_row  = lid & 15;
    const int a_koff = (lid >> 4) * 8;
    const int bx_row  = (lid & 7) + (lid >> 4) * 8;
    const int bx_koff = ((lid >> 3) & 1) * 8;

    float acc[2][8][4];
    #pragma unroll
    for (int i = 0; i < 2; i++)
        #pragma unroll
        for (int j = 0; j < 8; j++)
            #pragma unroll
            for (int c = 0; c < 4; c++) acc[i][j][c] = 0.f;

    // ---- stage issue (cp.async) ----
    auto issue_stage = [&](int kc, int s) {
        const int k0 = kc * 32;
        const uint32_t base = uS + s * QK_STAGE;
        #pragma unroll
        for (int it = 0; it < 4; it++) {
            int f = tid + it * 256;
            int arr = f >> 9, g = f & 511;
            int row = g >> 2, u = g & 3;
            const __nv_bfloat16* src = (arr ? g_xl : g_xh) + (size_t)(m0 + row) * NH + k0 + u * 8;
            cp_async16(base + (arr ? QK_ALO : QK_AHI) + (uint32_t)(row * QK_ASTRIDE + u * 8) * 2, src);
        }
        #pragma unroll
        for (int it = 0; it < 4; it++) {
            int f = tid + it * 256;
            int arr = f >> 9, g = f & 511;
            int row = g >> 2, u = g & 3;
            const __nv_bfloat16* src = (arr ? Wlo : Whi) + (size_t)row * NH + k0 + u * 8;
            cp_async16(base + (arr ? QK_BLO : QK_BHI) + (uint32_t)(row * QK_ASTRIDE + u * 8) * 2, src);
        }
        CP_COMMIT();
    };

    issue_stage(0, 0);

    for (int kc = 0; kc < 32; kc++) {
        if (kc < 31) issue_stage(kc + 1, (kc + 1) & 1);
        if (kc < 31) { CP_WAIT(1); } else { CP_WAIT(0); }
        __syncthreads();

        const uint32_t base = uS + (kc & 1) * QK_STAGE;
        #pragma unroll
        for (int ks = 0; ks < 2; ks++) {
            uint32_t ahi[2][4], alo[2][4];
            #pragma unroll
            for (int mi = 0; mi < 2; mi++) {
                uint32_t off = ((warpM + mi * 16 + a_row) * QK_ASTRIDE + ks * 16 + a_koff) * 2;
                ldsm_x4(ahi[mi], base + QK_AHI + off);
                ldsm_x4(alo[mi], base + QK_ALO + off);
            }
            #pragma unroll
            for (int njp = 0; njp < 4; njp++) {
                uint32_t boff = ((warpN + njp * 16 + bx_row) * QK_ASTRIDE + ks * 16 + bx_koff) * 2;
                uint32_t bh[4], bl[4];
                ldsm_x4(bh, base + QK_BHI + boff);
                ldsm_x4(bl, base + QK_BLO + boff);
                #pragma unroll
                for (int h = 0; h < 2; h++) {
                    #pragma unroll
                    for (int mi = 0; mi < 2; mi++) {
                        mma16816(acc[mi][njp * 2 + h], ahi[mi], &bh[h * 2]);
                        mma16816(acc[mi][njp * 2 + h], ahi[mi], &bl[h * 2]);
                        mma16816(acc[mi][njp * 2 + h], alo[mi], &bh[h * 2]);
                    }
                }
            }
        }
        __syncthreads();
    }

    // epilogue: bias add, (q: scale), split-bf16 stores
    #pragma unroll
    for (int mi = 0; mi < 2; mi++) {
        #pragma unroll
        for (int nj = 0; nj < 8; nj++) {
            int r0 = m0 + warpM + mi * 16 + (lid >> 2);
            int c0 = warpN + nj * 8 + (lid & 3) * 2;
            float b0 = bias[c0], b1 = bias[c0 + 1];
            float v0 = (acc[mi][nj][0] + b0) * oscale;
            float v1 = (acc[mi][nj][1] + b1) * oscale;
            float v2 = (acc[mi][nj][2] + b0) * oscale;
            float v3 = (acc[mi][nj][3] + b1) * oscale;
            uint32_t h01, l01, h23, l23;
            split2(v0, v1, h01, l01);
            split2(v2, v3, h23, l23);
            *(uint32_t*)&outh[(size_t)r0 * ND + c0] = h01;
            *(uint32_t*)&outl[(size_t)r0 * ND + c0] = l01;
            *(uint32_t*)&outh[(size_t)(r0 + 8) * ND + c0] = h23;
            *(uint32_t*)&outl[(size_t)(r0 + 8) * ND + c0] = l23;
        }
    }
}

// ---------------------------------------------------------------------------
// Attention: per CTA = (batch, 32-query tile), 256 threads.
// Q frags cached in registers; 64-row K/V chunks double-buffered via cp.async;
// P frags built directly from Ss (fp32) with inline split.
// ---------------------------------------------------------------------------
#define QSTRIDE 136
#define SS_STRIDE 1032
#define OFF_QH 0
#define OFF_QL (32 * QSTRIDE * 2)                 // 8704
#define OFF_K  (OFF_QL + 32 * QSTRIDE * 2)        // 17408
#define K_HALF (64 * QSTRIDE * 2)                 // 17408
#define KSTAGE (2 * K_HALF)                       // 34816
#define OFF_SS (OFF_K + 2 * KSTAGE)               // 87040
#define OFF_RED (OFF_SS + 32 * SS_STRIDE * 4)     // 219136
#define ATTN_SMEM_BYTES (OFF_RED + 128)           // 219264

__global__ __launch_bounds__(256, 1) void attn_kernel(float* __restrict__ o_out,
                                                      float* __restrict__ o_probs)
{
    extern __shared__ char smem[];
    float* Ss  = (float*)(smem + OFF_SS);
    float* red = (float*)(smem + OFF_RED);
    const uint32_t uB = smem_u32(smem);

    const int tid = threadIdx.x;
    const int wid = tid >> 5, lid = tid & 31;
    const int b  = blockIdx.y;
    const int q0 = blockIdx.x * 32;

    const int a_row  = lid & 15;
    const int a_koff = (lid >> 4) * 8;
    const int bq_row  = lid & 7;                    // ldsm_x2 (n=8)
    const int bq_koff = ((lid >> 3) & 1) * 8;
    const int t_krow = (lid & 7) + ((lid >> 3) & 1) * 8;
    const int t_ncol = (lid >> 4) * 8;

    // ---- issue Q stage (cp.async, group 0) ----
    #pragma unroll
    for (int it = 0; it < 4; it++) {
        int f = tid + it * 256;              // 0..1023
        int arr = f >> 9, g = f & 511;
        int row = g >> 4, u = g & 15;
        const __nv_bfloat16* src = (arr ? g_ql : g_qh) + ((size_t)(b * NS + q0 + row)) * ND + u * 8;
        cp_async16(uB + (arr ? OFF_QL : OFF_QH) + (uint32_t)(row * QSTRIDE + u * 8) * 2, src);
    }
    CP_COMMIT();

    // ---- 64-row chunk stage (K or V) ----
    auto stage_chunk = [&](const __nv_bfloat16* srcH, const __nv_bfloat16* srcL,
                           int chunk, int s) {
        const size_t gbase = ((size_t)(b * NS + chunk * 64)) * ND;
        const uint32_t base = uB + OFF_K + s * KSTAGE;
        #pragma unroll
        for (int it = 0; it < 8; it++) {
            int f = tid + it * 256;          // 0..2047
            int arr = f >> 10, g = f & 1023;
            int row = g >> 4, u = g & 15;
            const __nv_bfloat16* src = (arr ? srcL : srcH) + gbase + (size_t)row * ND + u * 8;
            cp_async16(base + arr * K_HALF + (uint32_t)(row * QSTRIDE + u * 8) * 2, src);
        }
        CP_COMMIT();
    };

    stage_chunk(g_kh, g_kl, 0, 0);
    CP_WAIT(1);            // Q done (K0 outstanding)
    __syncthreads();

    // ---- preload Q fragments (invariant across all chunks) ----
    uint32_t qfh[8][2][4], qfl[8][2][4];
    #pragma unroll
    for (int ks = 0; ks < 8; ks++) {
        #pragma unroll
        for (int mi = 0; mi < 2; mi++) {
            uint32_t off = ((mi * 16 + a_row) * QSTRIDE + ks * 16 + a_koff) * 2;
            ldsm_x4(qfh[ks][mi], uB + OFF_QH + off);
            ldsm_x4(qfl[ks][mi], uB + OFF_QL + off);
        }
    }

    // ================= phase 1: S = Q @ K^T (16 chunks of 64 keys) ==========
    for (int kc = 0; kc < 16; kc++) {
        if (kc < 15) stage_chunk(g_kh, g_kl, kc + 1, (kc + 1) & 1);
        if (kc < 15) { CP_WAIT(1); } else { CP_WAIT(0); }
        __syncthreads();

        const uint32_t kb = uB + OFF_K + (kc & 1) * KSTAGE;
        float acc[2][4];
        #pragma unroll
        for (int mi = 0; mi < 2; mi++)
            #pragma unroll
            for (int c = 0; c < 4; c++) acc[mi][c] = 0.f;

        #pragma unroll
        for (int ks = 0; ks < 8; ks++) {
            uint32_t boff = ((wid * 8 + bq_row) * QSTRIDE + ks * 16 + bq_koff) * 2;
            uint32_t bh[2], bl[2];
            ldsm_x2(bh, kb + boff);
            ldsm_x2(bl, kb + K_HALF + boff);
            #pragma unroll
            for (int mi = 0; mi < 2; mi++) {
                mma16816(acc[mi], qfh[ks][mi], bh);
                mma16816(acc[mi], qfh[ks][mi], bl);
                mma16816(acc[mi], qfl[ks][mi], bh);
            }
        }
        #pragma unroll
        for (int mi = 0; mi < 2; mi++) {
            int row0 = mi * 16 + (lid >> 2);
            int col  = kc * 64 + wid * 8 + (lid & 3) * 2;
            *(float2*)&Ss[row0 * SS_STRIDE + col]       = make_float2(acc[mi][0], acc[mi][1]);
            *(float2*)&Ss[(row0 + 8) * SS_STRIDE + col] = make_float2(acc[mi][2], acc[mi][3]);
        }
        __syncthreads();
    }

    // prefetch V chunk 0 (hides behind softmax)
    stage_chunk(g_vh, g_vl, 0, 0);

    // ================= softmax (8 threads/row, poly exp) =================
    {
        int rr = tid >> 3;
        int j  = tid & 7;
        float* row = &Ss[rr * SS_STRIDE];
        float mx = -1e30f;
        #pragma unroll 8
        for (int tt = 0; tt < 128; tt++) mx = fmaxf(mx, row[j + 8 * tt]);
        #pragma unroll
        for (int o = 1; o < 8; o <<= 1) mx = fmaxf(mx, __shfl_xor_sync(0xffffffffu, mx, o));
        float sum = 0.f;
        #pragma unroll 8
        for (int tt = 0; tt < 128; tt++) {
            int idx = j + 8 * tt;
            float e = fast_exp(row[idx] - mx);
            row[idx] = e;
            sum += e;
        }
        #pragma unroll
        for (int o = 1; o < 8; o <<= 1) sum += __shfl_xor_sync(0xffffffffu, sum, o);
        if (j == 0) red[rr] = 1.f / sum;
    }
    __syncthreads();

    // ================= probs write (normalized) =================
    #pragma unroll 4
    for (int it = 0; it < 32; it++) {
        int f  = tid + it * 256;
        int rr = f >> 8;
        int c4 = (f & 255) * 4;
        float ri = red[rr];
        float4 e = *(const float4*)&Ss[rr * SS_STRIDE + c4];
        e.x *= ri; e.y *= ri; e.z *= ri; e.w *= ri;
        *(float4*)&o_probs[((size_t)(b * NS + q0 + rr)) * NS + c4] = e;
    }
    __syncthreads();

    // ================= phase 3: O = (E @ V) * 1/sum (16 chunks) ============
    float acc2[2][2][4];
    #pragma unroll
    for (int mi = 0; mi < 2; mi++)
        #pragma unroll
        for (int nt = 0; nt < 2; nt++)
            #pragma unroll
            for (int c = 0; c < 4; c++) acc2[mi][nt][c] = 0.f;

    for (int vc = 0; vc < 16; vc++) {
        if (vc < 15) stage_chunk(g_vh, g_vl, vc + 1, (vc + 1) & 1);
        if (vc < 15) { CP_WAIT(1); } else { CP_WAIT(0); }
        __syncthreads();

        const uint32_t vb = uB + OFF_K + (vc & 1) * KSTAGE;
        #pragma unroll
        for (int ks = 0; ks < 4; ks++) {
            // P fragments directly from Ss (fp32 -> split bf16 inline)
            uint32_t ph[2][4], pl[2][4];
            #pragma unroll
            for (int mi = 0; mi < 2; mi++) {
                int row  = mi * 16 + (lid >> 2);
                int kcol = vc * 64 + ks * 16 + (lid & 3) * 2;
                float2 p0 = *(const float2*)&Ss[row * SS_STRIDE + kcol];
                float2 p1 = *(const float2*)&Ss[(row + 8) * SS_STRIDE + kcol];
                float2 p2 = *(const float2*)&Ss[row * SS_STRIDE + kcol + 8];
                float2 p3 = *(const float2*)&Ss[(row + 8) * SS_STRIDE + kcol + 8];
                split2(p0.x, p0.y, ph[mi][0], pl[mi][0]);
                split2(p1.x, p1.y, ph[mi][1], pl[mi][1]);
                split2(p2.x, p2.y, ph[mi][2], pl[mi][2]);
                split2(p3.x, p3.y, ph[mi][3], pl[mi][3]);
            }
            uint32_t toff = ((ks * 16 + t_krow) * QSTRIDE + wid * 16 + t_ncol) * 2;
            uint32_t vh[4], vl[4];
            ldsm_x4_t(vh, vb + toff);
            ldsm_x4_t(vl, vb + K_HALF + toff);
            #pragma unroll
            for (int nt = 0; nt < 2; nt++) {
                #pragma unroll
                for (int mi = 0; mi < 2; mi++) {
                    mma16816(acc2[mi][nt], ph[mi], &vh[nt * 2]);
                    mma16816(acc2[mi][nt], ph[mi], &vl[nt * 2]);
                    mma16816(acc2[mi][nt], pl[mi], &vh[nt * 2]);
                }
            }
        }
        __syncthreads();
    }

    // ---- epilogue: O = acc2 * 1/sum ----
    #pragma unroll
    for (int mi = 0; mi < 2; mi++) {
        #pragma unroll
        for (int nt = 0; nt < 2; nt++) {
            int row0 = mi * 16 + (lid >> 2);
            int col  = wid * 16 + nt * 8 + (lid & 3) * 2;
            float r1 = red[row0], r2 = red[row0 + 8];
            *(float2*)&o_out[((size_t)(b * NS + q0 + row0)) * ND + col] =
                make_float2(acc2[mi][nt][0] * r1, acc2[mi][nt][1] * r1);
            *(float2*)&o_out[((size_t)(b * NS + q0 + row0 + 8)) * ND + col] =
                make_float2(acc2[mi][nt][2] * r2, acc2[mi][nt][3] * r2);
        }
    }
}

// ---------------------------------------------------------------------------
extern "C" void kernel_launch(void* const* d_in, const int* in_sizes, int n_in,
                              void* d_out, int out_size)
{
    const float* X  = (const float*)d_in[0];
    const float* Wq = (const float*)d_in[1];
    const float* bq = (const float*)d_in[2];
    const float* Wk = (const float*)d_in[3];
    const float* bk = (const float*)d_in[4];
    const float* Wv = (const float*)d_in[5];
    const float* bv = (const float*)d_in[6];

    float* out   = (float*)d_out;                 // [32,1024,128]
    float* probs = out + (size_t)NB * NS * ND;    // [32,1024,1024]

    cudaFuncSetAttribute(qkv_mma_kernel, cudaFuncAttributeMaxDynamicSharedMemorySize, QK_SMEM);
    cudaFuncSetAttribute(attn_kernel, cudaFuncAttributeMaxDynamicSharedMemorySize,
                         ATTN_SMEM_BYTES);

    convx_kernel<<<8192, 256>>>(X);
    convw_kernel<<<48, 256>>>(Wq, Wk, Wv);
    qkv_mma_kernel<<<dim3(256, 3), 256, QK_SMEM>>>(bq, bk, bv);
    attn_kernel<<<dim3(32, 32), 256, ATTN_SMEM_BYTES>>>(out, probs);
}

// round 6
// speedup vs baseline: 3.3709x; 1.3142x over previous
#include <cuda_runtime.h>
#include <cuda_bf16.h>
#include <cstdint>
#include <math.h>

#define NB 32
#define NS 1024
#define NH 1024
#define ND 128

// persistent scratch (__device__ globals per allocation rules) — split bf16
__device__ __nv_bfloat16 g_xh[NB * NS * NH];
__device__ __nv_bfloat16 g_xl[NB * NS * NH];
__device__ __nv_bfloat16 g_qh[NB * NS * ND];
__device__ __nv_bfloat16 g_ql[NB * NS * ND];
__device__ __nv_bfloat16 g_kh[NB * NS * ND];
__device__ __nv_bfloat16 g_kl[NB * NS * ND];
__device__ __nv_bfloat16 g_vh[NB * NS * ND];
__device__ __nv_bfloat16 g_vl[NB * NS * ND];
__device__ __nv_bfloat16 g_ph[NB * NS * NS];   // split normalized probs
__device__ __nv_bfloat16 g_pl[NB * NS * NS];
__device__ __nv_bfloat16 g_wthi[3 * ND * NH];  // [w][n][k]
__device__ __nv_bfloat16 g_wtlo[3 * ND * NH];

// ---------------------------------------------------------------------------
// helpers
// ---------------------------------------------------------------------------
__device__ __forceinline__ uint32_t smem_u32(const void* p) {
    uint32_t a;
    asm("{ .reg .u64 t; cvta.to.shared.u64 t, %1; cvt.u32.u64 %0, t; }" : "=r"(a) : "l"(p));
    return a;
}
__device__ __forceinline__ void ldsm_x4(uint32_t* r, uint32_t addr) {
    asm volatile("ldmatrix.sync.aligned.m8n8.x4.shared.b16 {%0,%1,%2,%3}, [%4];"
                 : "=r"(r[0]), "=r"(r[1]), "=r"(r[2]), "=r"(r[3]) : "r"(addr));
}
__device__ __forceinline__ void ldsm_x4_t(uint32_t* r, uint32_t addr) {
    asm volatile("ldmatrix.sync.aligned.m8n8.x4.trans.shared.b16 {%0,%1,%2,%3}, [%4];"
                 : "=r"(r[0]), "=r"(r[1]), "=r"(r[2]), "=r"(r[3]) : "r"(addr));
}
__device__ __forceinline__ void mma16816(float* d, const uint32_t* a, const uint32_t* b) {
    asm volatile(
        "mma.sync.aligned.m16n8k16.row.col.f32.bf16.bf16.f32 "
        "{%0,%1,%2,%3}, {%4,%5,%6,%7}, {%8,%9}, {%0,%1,%2,%3};"
        : "+f"(d[0]), "+f"(d[1]), "+f"(d[2]), "+f"(d[3])
        : "r"(a[0]), "r"(a[1]), "r"(a[2]), "r"(a[3]), "r"(b[0]), "r"(b[1]));
}
__device__ __forceinline__ void split2(float a, float b, uint32_t& hi, uint32_t& lo) {
    __nv_bfloat16 ha = __float2bfloat16(a), hb = __float2bfloat16(b);
    __nv_bfloat16 la = __float2bfloat16(a - __bfloat162float(ha));
    __nv_bfloat16 lb = __float2bfloat16(b - __bfloat162float(hb));
    hi = (uint32_t)__bfloat16_as_ushort(ha) | ((uint32_t)__bfloat16_as_ushort(hb) << 16);
    lo = (uint32_t)__bfloat16_as_ushort(la) | ((uint32_t)__bfloat16_as_ushort(lb) << 16);
}
__device__ __forceinline__ float fast_exp(float x) {
    float t = x * 1.4426950408889634f;
    int ii = __float2int_rn(t);
    float f = t - (float)ii;
    float y = f * 0.6931471805599453f;
    float p = 1.0f + y * (1.0f + y * (0.5f + y * (0.16666667f + y * (0.041666668f + y * 0.008333334f))));
    return __int_as_float(__float_as_int(p) + (ii << 23));
}
__device__ __forceinline__ void cp_async16(uint32_t smem_addr, const void* gptr) {
    asm volatile("cp.async.cg.shared.global [%0], [%1], 16;" :: "r"(smem_addr), "l"(gptr));
}
#define CP_COMMIT() asm volatile("cp.async.commit_group;" ::: "memory")
#define CP_WAIT(n)  asm volatile("cp.async.wait_group %0;" :: "n"(n) : "memory")

// ---------------------------------------------------------------------------
// X split
// ---------------------------------------------------------------------------
__global__ __launch_bounds__(256) void convx_kernel(const float* __restrict__ X)
{
    const int total = NB * NS * NH / 4;
    for (int i = blockIdx.x * 256 + threadIdx.x; i < total; i += gridDim.x * 256) {
        float4 v = ((const float4*)X)[i];
        uint2 h, l;
        split2(v.x, v.y, h.x, l.x);
        split2(v.z, v.w, h.y, l.y);
        ((uint2*)g_xh)[i] = h;
        ((uint2*)g_xl)[i] = l;
    }
}

// ---------------------------------------------------------------------------
// Weight transpose+split
// ---------------------------------------------------------------------------
__global__ __launch_bounds__(256) void convw_kernel(
    const float* __restrict__ Wq, const float* __restrict__ Wk, const float* __restrict__ Wv)
{
    __shared__ float sW[64 * 129];
    int w = blockIdx.x >> 4;
    int k0 = (blockIdx.x & 15) * 64;
    const float* W = (w == 0) ? Wq : (w == 1) ? Wk : Wv;
    int tid = threadIdx.x;

    #pragma unroll
    for (int it = 0; it < 32; it++) {
        int f = tid + it * 256;
        int kk = f >> 7, n = f & 127;
        sW[kk * 129 + n] = W[(size_t)(k0 + kk) * ND + n];
    }
    __syncthreads();

    #pragma unroll
    for (int it = 0; it < 32; it++) {
        int f = tid + it * 256;
        int n = f >> 6, kk = f & 63;
        float x = sW[kk * 129 + n];
        __nv_bfloat16 hi = __float2bfloat16(x);
        __nv_bfloat16 lo = __float2bfloat16(x - __bfloat162float(hi));
        size_t di = (size_t)w * ND * NH + (size_t)n * NH + k0 + kk;
        g_wthi[di] = hi;
        g_wtlo[di] = lo;
    }
}

// ---------------------------------------------------------------------------
// QKV GEMM: 2-stage cp.async, BM=128 BN=128 BK=32, 2 CTAs/SM.
// ---------------------------------------------------------------------------
#define TSTRIDE 40
#define QK_AHI 0
#define QK_ALO 10240
#define QK_BHI 20480
#define QK_BLO 30720
#define QK_STAGE 40960
#define QK_SMEM (2 * QK_STAGE)

__global__ __launch_bounds__(256, 2) void qkv_mma_kernel(
    const float* __restrict__ bq, const float* __restrict__ bk, const float* __restrict__ bv)
{
    extern __shared__ char sm[];
    const uint32_t uS = smem_u32(sm);

    const int tid = threadIdx.x;
    const int wid = tid >> 5, lid = tid & 31;
    const int m0 = blockIdx.x * 128;
    const int w  = blockIdx.y;

    const __nv_bfloat16* Whi = g_wthi + (size_t)w * ND * NH;
    const __nv_bfloat16* Wlo = g_wtlo + (size_t)w * ND * NH;
    const float* bias = (w == 0) ? bq : (w == 1) ? bk : bv;
    __nv_bfloat16* outh = (w == 0) ? g_qh : (w == 1) ? g_kh : g_vh;
    __nv_bfloat16* outl = (w == 0) ? g_ql : (w == 1) ? g_kl : g_vl;
    const float oscale = (w == 0) ? 0.08838834764831845f : 1.0f;

    const int warpM = (wid >> 1) * 32;
    const int warpN = (wid & 1) * 64;

    const int a_row  = lid & 15;
    const int a_koff = (lid >> 4) * 8;
    const int bx_row  = (lid & 7) + (lid >> 4) * 8;
    const int bx_koff = ((lid >> 3) & 1) * 8;

    float acc[2][8][4];
    #pragma unroll
    for (int i = 0; i < 2; i++)
        #pragma unroll
        for (int j = 0; j < 8; j++)
            #pragma unroll
            for (int c = 0; c < 4; c++) acc[i][j][c] = 0.f;

    auto issue_stage = [&](int kc, int s) {
        const int k0 = kc * 32;
        const uint32_t base = uS + s * QK_STAGE;
        #pragma unroll
        for (int it = 0; it < 4; it++) {
            int f = tid + it * 256;
            int arr = f >> 9, g = f & 511;
            int row = g >> 2, u = g & 3;
            const __nv_bfloat16* src = (arr ? g_xl : g_xh) + (size_t)(m0 + row) * NH + k0 + u * 8;
            cp_async16(base + (arr ? QK_ALO : QK_AHI) + (uint32_t)(row * TSTRIDE + u * 8) * 2, src);
        }
        #pragma unroll
        for (int it = 0; it < 4; it++) {
            int f = tid + it * 256;
            int arr = f >> 9, g = f & 511;
            int row = g >> 2, u = g & 3;
            const __nv_bfloat16* src = (arr ? Wlo : Whi) + (size_t)row * NH + k0 + u * 8;
            cp_async16(base + (arr ? QK_BLO : QK_BHI) + (uint32_t)(row * TSTRIDE + u * 8) * 2, src);
        }
        CP_COMMIT();
    };

    issue_stage(0, 0);

    for (int kc = 0; kc < 32; kc++) {
        if (kc < 31) { issue_stage(kc + 1, (kc + 1) & 1); CP_WAIT(1); }
        else         { CP_WAIT(0); }
        __syncthreads();

        const uint32_t base = uS + (kc & 1) * QK_STAGE;
        #pragma unroll
        for (int ks = 0; ks < 2; ks++) {
            uint32_t ahi[2][4], alo[2][4];
            #pragma unroll
            for (int mi = 0; mi < 2; mi++) {
                uint32_t off = ((warpM + mi * 16 + a_row) * TSTRIDE + ks * 16 + a_koff) * 2;
                ldsm_x4(ahi[mi], base + QK_AHI + off);
                ldsm_x4(alo[mi], base + QK_ALO + off);
            }
            #pragma unroll
            for (int njp = 0; njp < 4; njp++) {
                uint32_t boff = ((warpN + njp * 16 + bx_row) * TSTRIDE + ks * 16 + bx_koff) * 2;
                uint32_t bh[4], bl[4];
                ldsm_x4(bh, base + QK_BHI + boff);
                ldsm_x4(bl, base + QK_BLO + boff);
                #pragma unroll
                for (int h = 0; h < 2; h++) {
                    #pragma unroll
                    for (int mi = 0; mi < 2; mi++) {
                        mma16816(acc[mi][njp * 2 + h], ahi[mi], &bh[h * 2]);
                        mma16816(acc[mi][njp * 2 + h], ahi[mi], &bl[h * 2]);
                        mma16816(acc[mi][njp * 2 + h], alo[mi], &bh[h * 2]);
                    }
                }
            }
        }
        __syncthreads();
    }

    #pragma unroll
    for (int mi = 0; mi < 2; mi++) {
        #pragma unroll
        for (int nj = 0; nj < 8; nj++) {
            int r0 = m0 + warpM + mi * 16 + (lid >> 2);
            int c0 = warpN + nj * 8 + (lid & 3) * 2;
            float b0 = bias[c0], b1 = bias[c0 + 1];
            float v0 = (acc[mi][nj][0] + b0) * oscale;
            float v1 = (acc[mi][nj][1] + b1) * oscale;
            float v2 = (acc[mi][nj][2] + b0) * oscale;
            float v3 = (acc[mi][nj][3] + b1) * oscale;
            uint32_t h01, l01, h23, l23;
            split2(v0, v1, h01, l01);
            split2(v2, v3, h23, l23);
            *(uint32_t*)&outh[(size_t)r0 * ND + c0] = h01;
            *(uint32_t*)&outl[(size_t)r0 * ND + c0] = l01;
            *(uint32_t*)&outh[(size_t)(r0 + 8) * ND + c0] = h23;
            *(uint32_t*)&outl[(size_t)(r0 + 8) * ND + c0] = l23;
        }
    }
}

// ---------------------------------------------------------------------------
// score_kernel: raw S = q_scaled @ k^T -> probs buffer (fp32).
// grid(8 qtile, 8 ktile, 32 b), CTA 128x128, BK=32, 4 chunks, 2 CTAs/SM.
// ---------------------------------------------------------------------------
__global__ __launch_bounds__(256, 2) void score_kernel(float* __restrict__ probs)
{
    extern __shared__ char sm[];
    const uint32_t uS = smem_u32(sm);

    const int tid = threadIdx.x;
    const int wid = tid >> 5, lid = tid & 31;
    const int m0 = blockIdx.x * 128;
    const int n0 = blockIdx.y * 128;
    const int b  = blockIdx.z;
    const size_t qbase = (size_t)(b * NS + m0) * ND;
    const size_t kbase = (size_t)(b * NS + n0) * ND;

    const int warpM = (wid >> 1) * 32;
    const int warpN = (wid & 1) * 64;
    const int a_row  = lid & 15;
    const int a_koff = (lid >> 4) * 8;
    const int bx_row  = (lid & 7) + (lid >> 4) * 8;
    const int bx_koff = ((lid >> 3) & 1) * 8;

    float acc[2][8][4];
    #pragma unroll
    for (int i = 0; i < 2; i++)
        #pragma unroll
        for (int j = 0; j < 8; j++)
            #pragma unroll
            for (int c = 0; c < 4; c++) acc[i][j][c] = 0.f;

    auto issue_stage = [&](int kc, int s) {
        const int k0 = kc * 32;
        const uint32_t base = uS + s * QK_STAGE;
        #pragma unroll
        for (int it = 0; it < 4; it++) {
            int f = tid + it * 256;
            int arr = f >> 9, g = f & 511;
            int row = g >> 2, u = g & 3;
            const __nv_bfloat16* src = (arr ? g_ql : g_qh) + qbase + (size_t)row * ND + k0 + u * 8;
            cp_async16(base + (arr ? QK_ALO : QK_AHI) + (uint32_t)(row * TSTRIDE + u * 8) * 2, src);
        }
        #pragma unroll
        for (int it = 0; it < 4; it++) {
            int f = tid + it * 256;
            int arr = f >> 9, g = f & 511;
            int row = g >> 2, u = g & 3;
            const __nv_bfloat16* src = (arr ? g_kl : g_kh) + kbase + (size_t)row * ND + k0 + u * 8;
            cp_async16(base + (arr ? QK_BLO : QK_BHI) + (uint32_t)(row * TSTRIDE + u * 8) * 2, src);
        }
        CP_COMMIT();
    };

    issue_stage(0, 0);

    for (int kc = 0; kc < 4; kc++) {
        if (kc < 3) { issue_stage(kc + 1, (kc + 1) & 1); CP_WAIT(1); }
        else        { CP_WAIT(0); }
        __syncthreads();

        const uint32_t base = uS + (kc & 1) * QK_STAGE;
        #pragma unroll
        for (int ks = 0; ks < 2; ks++) {
            uint32_t ahi[2][4], alo[2][4];
            #pragma unroll
            for (int mi = 0; mi < 2; mi++) {
                uint32_t off = ((warpM + mi * 16 + a_row) * TSTRIDE + ks * 16 + a_koff) * 2;
                ldsm_x4(ahi[mi], base + QK_AHI + off);
                ldsm_x4(alo[mi], base + QK_ALO + off);
            }
            #pragma unroll
            for (int njp = 0; njp < 4; njp++) {
                uint32_t boff = ((warpN + njp * 16 + bx_row) * TSTRIDE + ks * 16 + bx_koff) * 2;
                uint32_t bh[4], bl[4];
                ldsm_x4(bh, base + QK_BHI + boff);
                ldsm_x4(bl, base + QK_BLO + boff);
                #pragma unroll
                for (int h = 0; h < 2; h++) {
                    #pragma unroll
                    for (int mi = 0; mi < 2; mi++) {
                        mma16816(acc[mi][njp * 2 + h], ahi[mi], &bh[h * 2]);
                        mma16816(acc[mi][njp * 2 + h], ahi[mi], &bl[h * 2]);
                        mma16816(acc[mi][njp * 2 + h], alo[mi], &bh[h * 2]);
                    }
                }
            }
        }
        __syncthreads();
    }

    float* pb = probs + (size_t)b * NS * NS;
    #pragma unroll
    for (int mi = 0; mi < 2; mi++) {
        #pragma unroll
        for (int nj = 0; nj < 8; nj++) {
            int r0 = m0 + warpM + mi * 16 + (lid >> 2);
            int c0 = n0 + warpN + nj * 8 + (lid & 3) * 2;
            *(float2*)&pb[(size_t)r0 * NS + c0]       = make_float2(acc[mi][nj][0], acc[mi][nj][1]);
            *(float2*)&pb[(size_t)(r0 + 8) * NS + c0] = make_float2(acc[mi][nj][2], acc[mi][nj][3]);
        }
    }
}

// ---------------------------------------------------------------------------
// softmax_kernel: warp per row, register resident.
// normalizes probs in place + writes split-bf16 P to g_ph/g_pl.
// ---------------------------------------------------------------------------
__global__ __launch_bounds__(256) void softmax_kernel(float* __restrict__ probs)
{
    const int wid = threadIdx.x >> 5, lid = threadIdx.x & 31;
    const int row = blockIdx.x * 8 + wid;   // 0..32767
    const size_t base4 = (size_t)row * (NS / 4);

    float4 v[8];
    #pragma unroll
    for (int u = 0; u < 8; u++) v[u] = ((const float4*)probs)[base4 + lid + u * 32];

    float mx = -1e30f;
    #pragma unroll
    for (int u = 0; u < 8; u++) {
        mx = fmaxf(mx, fmaxf(fmaxf(v[u].x, v[u].y), fmaxf(v[u].z, v[u].w)));
    }
    #pragma unroll
    for (int o = 1; o < 32; o <<= 1) mx = fmaxf(mx, __shfl_xor_sync(0xffffffffu, mx, o));

    float sum = 0.f;
    #pragma unroll
    for (int u = 0; u < 8; u++) {
        v[u].x = fast_exp(v[u].x - mx);
        v[u].y = fast_exp(v[u].y - mx);
        v[u].z = fast_exp(v[u].z - mx);
        v[u].w = fast_exp(v[u].w - mx);
        sum += (v[u].x + v[u].y) + (v[u].z + v[u].w);
    }
    #pragma unroll
    for (int o = 1; o < 32; o <<= 1) sum += __shfl_xor_sync(0xffffffffu, sum, o);
    const float inv = 1.f / sum;

    #pragma unroll
    for (int u = 0; u < 8; u++) {
        v[u].x *= inv; v[u].y *= inv; v[u].z *= inv; v[u].w *= inv;
        ((float4*)probs)[base4 + lid + u * 32] = v[u];
        uint2 h, l;
        split2(v[u].x, v[u].y, h.x, l.x);
        split2(v[u].z, v[u].w, h.y, l.y);
        ((uint2*)g_ph)[base4 + lid + u * 32] = h;
        ((uint2*)g_pl)[base4 + lid + u * 32] = l;
    }
}

// ---------------------------------------------------------------------------
// pv_kernel: O = P @ V. grid(8 qtile, 32 b), CTA 128x128(d), K=1024, BK=32.
// P frags normal ldsm (stride 40); V frags trans ldsm (stride 136). 2 CTAs/SM.
// ---------------------------------------------------------------------------
#define PV_PHI 0
#define PV_PLO 10240
#define PV_VHI 20480
#define PV_VLO 29184
#define PV_STAGE 37888
#define PV_SMEM (2 * PV_STAGE)
#define VSTRIDE 136

__global__ __launch_bounds__(256, 2) void pv_kernel(float* __restrict__ o_out)
{
    extern __shared__ char sm[];
    const uint32_t uS = smem_u32(sm);

    const int tid = threadIdx.x;
    const int wid = tid >> 5, lid = tid & 31;
    const int m0 = blockIdx.x * 128;
    const int b  = blockIdx.y;
    const size_t pbase = (size_t)(b * NS + m0) * NS;
    const size_t vbase = (size_t)(b * NS) * ND;

    const int warpM = (wid >> 1) * 32;
    const int warpN = (wid & 1) * 64;
    const int a_row  = lid & 15;
    const int a_koff = (lid >> 4) * 8;
    const int t_krow = (lid & 7) + ((lid >> 3) & 1) * 8;
    const int t_ncol = (lid >> 4) * 8;

    float acc[2][8][4];
    #pragma unroll
    for (int i = 0; i < 2; i++)
        #pragma unroll
        for (int j = 0; j < 8; j++)
            #pragma unroll
            for (int c = 0; c < 4; c++) acc[i][j][c] = 0.f;

    auto issue_stage = [&](int kc, int s) {
        const int k0 = kc * 32;
        const uint32_t base = uS + s * PV_STAGE;
        // P tile: 128 q-rows x 32 k (hi/lo)
        #pragma unroll
        for (int it = 0; it < 4; it++) {
            int f = tid + it * 256;
            int arr = f >> 9, g = f & 511;
            int row = g >> 2, u = g & 3;
            const __nv_bfloat16* src = (arr ? g_pl : g_ph) + pbase + (size_t)row * NS + k0 + u * 8;
            cp_async16(base + (arr ? PV_PLO : PV_PHI) + (uint32_t)(row * TSTRIDE + u * 8) * 2, src);
        }
        // V tile: 32 k-rows x 128 d (hi/lo)
        #pragma unroll
        for (int it = 0; it < 4; it++) {
            int f = tid + it * 256;
            int arr = f >> 9, g = f & 511;
            int row = g >> 4, u = g & 15;
            const __nv_bfloat16* src = (arr ? g_vl : g_vh) + vbase + (size_t)(k0 + row) * ND + u * 8;
            cp_async16(base + (arr ? PV_VLO : PV_VHI) + (uint32_t)(row * VSTRIDE + u * 8) * 2, src);
        }
        CP_COMMIT();
    };

    issue_stage(0, 0);

    for (int kc = 0; kc < 32; kc++) {
        if (kc < 31) { issue_stage(kc + 1, (kc + 1) & 1); CP_WAIT(1); }
        else         { CP_WAIT(0); }
        __syncthreads();

        const uint32_t base = uS + (kc & 1) * PV_STAGE;
        #pragma unroll
        for (int ks = 0; ks < 2; ks++) {
            uint32_t ph[2][4], pl[2][4];
            #pragma unroll
            for (int mi = 0; mi < 2; mi++) {
                uint32_t off = ((warpM + mi * 16 + a_row) * TSTRIDE + ks * 16 + a_koff) * 2;
                ldsm_x4(ph[mi], base + PV_PHI + off);
                ldsm_x4(pl[mi], base + PV_PLO + off);
            }
            #pragma unroll
            for (int njp = 0; njp < 4; njp++) {
                uint32_t toff = ((ks * 16 + t_krow) * VSTRIDE + warpN + njp * 16 + t_ncol) * 2;
                uint32_t vh[4], vl[4];
                ldsm_x4_t(vh, base + PV_VHI + toff);
                ldsm_x4_t(vl, base + PV_VLO + toff);
                #pragma unroll
                for (int h = 0; h < 2; h++) {
                    #pragma unroll
                    for (int mi = 0; mi < 2; mi++) {
                        mma16816(acc[mi][njp * 2 + h], ph[mi], &vh[h * 2]);
                        mma16816(acc[mi][njp * 2 + h], ph[mi], &vl[h * 2]);
                        mma16816(acc[mi][njp * 2 + h], pl[mi], &vh[h * 2]);
                    }
                }
            }
        }
        __syncthreads();
    }

    #pragma unroll
    for (int mi = 0; mi < 2; mi++) {
        #pragma unroll
        for (int nj = 0; nj < 8; nj++) {
            int r0 = m0 + warpM + mi * 16 + (lid >> 2);
            int c0 = warpN + nj * 8 + (lid & 3) * 2;
            *(float2*)&o_out[((size_t)(b * NS) + r0) * ND + c0] =
                make_float2(acc[mi][nj][0], acc[mi][nj][1]);
            *(float2*)&o_out[((size_t)(b * NS) + r0 + 8) * ND + c0] =
                make_float2(acc[mi][nj][2], acc[mi][nj][3]);
        }
    }
}

// ---------------------------------------------------------------------------
extern "C" void kernel_launch(void* const* d_in, const int* in_sizes, int n_in,
                              void* d_out, int out_size)
{
    const float* X  = (const float*)d_in[0];
    const float* Wq = (const float*)d_in[1];
    const float* bq = (const float*)d_in[2];
    const float* Wk = (const float*)d_in[3];
    const float* bk = (const float*)d_in[4];
    const float* Wv = (const float*)d_in[5];
    const float* bv = (const float*)d_in[6];

    float* out   = (float*)d_out;                 // [32,1024,128]
    float* probs = out + (size_t)NB * NS * ND;    // [32,1024,1024]

    cudaFuncSetAttribute(qkv_mma_kernel, cudaFuncAttributeMaxDynamicSharedMemorySize, QK_SMEM);
    cudaFuncSetAttribute(score_kernel, cudaFuncAttributeMaxDynamicSharedMemorySize, QK_SMEM);
    cudaFuncSetAttribute(pv_kernel, cudaFuncAttributeMaxDynamicSharedMemorySize, PV_SMEM);

    convx_kernel<<<8192, 256>>>(X);
    convw_kernel<<<48, 256>>>(Wq, Wk, Wv);
    qkv_mma_kernel<<<dim3(256, 3), 256, QK_SMEM>>>(bq, bk, bv);
    score_kernel<<<dim3(8, 8, 32), 256, QK_SMEM>>>(probs);
    softmax_kernel<<<4096, 256>>>(probs);
    pv_kernel<<<dim3(8, 32), 256, PV_SMEM>>>(out);
}